// round 10
// baseline (speedup 1.0000x reference)
#include <cuda_runtime.h>
#include <math.h>

#define BB 4
#define NN 65536
#define CC 192
#define HEADS 6
#define HEADC 32
#define MTOT (BB*NN)
#define TM 128
#define EPS 1e-5f
#define ASTR 196
#define WSTR 20
#define KVSTR 36

// only device-global scratch: tiny kv accumulator
__device__ float g_kv[BB * HEADS * HEADC * HEADC];

__global__ void zero_kv_kernel() {
    int i = blockIdx.x * blockDim.x + threadIdx.x;
    if (i < BB * HEADS * HEADC * HEADC) g_kv[i] = 0.f;
}

__device__ __forceinline__ unsigned f2tfu(float f) {
    unsigned u;
    asm("cvt.rna.tf32.f32 %0, %1;" : "=r"(u) : "f"(f));
    return u;
}
__device__ __forceinline__ float f2tff(float f) {     // tf32-truncated, as float bits
    return __uint_as_float(f2tfu(f));
}

__device__ __forceinline__ void mma8(float* c,
    unsigned a0, unsigned a1, unsigned a2, unsigned a3,
    unsigned b0, unsigned b1)
{
    asm volatile(
        "mma.sync.aligned.m16n8k8.row.col.f32.tf32.tf32.f32 "
        "{%0,%1,%2,%3}, {%4,%5,%6,%7}, {%8,%9}, {%0,%1,%2,%3};"
        : "+f"(c[0]), "+f"(c[1]), "+f"(c[2]), "+f"(c[3])
        : "r"(a0), "r"(a1), "r"(a2), "r"(a3), "r"(b0), "r"(b1));
}

// ---------------------------------------------------------------------------
// Kernel 1: k,v projection (one head per block) via TF32 mma, LN(k), LN(v),
// kv outer-product accumulation. All smem operands pre-converted to tf32 bits.
// grid: (HEADS, MTOT/TM), block: 256
// smem: As[2][128][20] + Wk[2][64][20] + Res[128][68] = 65,536 B
// ---------------------------------------------------------------------------
__global__ __launch_bounds__(256) void k1_kv(
    const float* __restrict__ x, const float* __restrict__ qkv_w,
    const float* __restrict__ qkv_b,
    const float* __restrict__ klw, const float* __restrict__ klb,
    const float* __restrict__ vlw, const float* __restrict__ vlb)
{
    extern __shared__ float sm[];
    float* As  = sm;                                   // 2*128*20
    float* Wk  = sm + 2 * 128 * WSTR;                  // 2*64*20
    float* Res = sm + 2 * 128 * WSTR + 2 * 64 * WSTR;  // 128*68

    const int tid  = threadIdx.x;
    const int head = blockIdx.x;
    const int m0   = blockIdx.y * TM;
    const int wbase = head * 96 + 32;              // k rows, then v rows

    const int warp = tid >> 5, lane = tid & 31;
    const int gid = lane >> 2, tig = lane & 3;
    const int m0w = (warp >> 1) * 32, n0w = (warp & 1) * 32;

    float4 xr[2], wreg;

    float acc[2][4][4];
    #pragma unroll
    for (int i = 0; i < 2; i++)
        #pragma unroll
        for (int j = 0; j < 4; j++)
            #pragma unroll
            for (int e = 0; e < 4; e++) acc[i][j][e] = 0.f;

    // prefetch chunk 0
    {
        #pragma unroll
        for (int t = 0; t < 2; t++) {
            int idx = tid + t * 256, p = idx >> 2, kk = (idx & 3) << 2;
            xr[t] = *(const float4*)&x[(size_t)(m0 + p) * CC + kk];
        }
        int d = tid >> 2, kk = (tid & 3) << 2;
        wreg = *(const float4*)&qkv_w[(size_t)(wbase + d) * CC + kk];
    }

    #pragma unroll 1
    for (int c = 0; c < 12; c++) {
        // STS chunk c (convert to tf32 bits once here)
        {
            #pragma unroll
            for (int t = 0; t < 2; t++) {
                int idx = tid + t * 256, p = idx >> 2, kk = (idx & 3) << 2;
                float* dst = &As[(c & 1) * 128 * WSTR + p * WSTR + kk];
                dst[0] = f2tff(xr[t].x); dst[1] = f2tff(xr[t].y);
                dst[2] = f2tff(xr[t].z); dst[3] = f2tff(xr[t].w);
            }
            int d = tid >> 2, kk = (tid & 3) << 2;
            float* dst = &Wk[(c & 1) * 64 * WSTR + d * WSTR + kk];
            dst[0] = f2tff(wreg.x); dst[1] = f2tff(wreg.y);
            dst[2] = f2tff(wreg.z); dst[3] = f2tff(wreg.w);
        }
        // LDG chunk c+1
        if (c < 11) {
            int k0 = (c + 1) * 16;
            #pragma unroll
            for (int t = 0; t < 2; t++) {
                int idx = tid + t * 256, p = idx >> 2, kk = (idx & 3) << 2;
                xr[t] = *(const float4*)&x[(size_t)(m0 + p) * CC + k0 + kk];
            }
            int d = tid >> 2, kk = (tid & 3) << 2;
            wreg = *(const float4*)&qkv_w[(size_t)(wbase + d) * CC + k0 + kk];
        }
        __syncthreads();
        const float* Ab = &As[(c & 1) * 128 * WSTR];
        const float* Wb = &Wk[(c & 1) * 64 * WSTR];
        #pragma unroll
        for (int s = 0; s < 2; s++) {
            int kk = 8 * s + tig;
            unsigned a[2][4];
            #pragma unroll
            for (int i = 0; i < 2; i++) {
                const float* ap = &Ab[(m0w + 16 * i + gid) * WSTR + kk];
                a[i][0] = __float_as_uint(ap[0]);
                a[i][1] = __float_as_uint(ap[8 * WSTR]);
                a[i][2] = __float_as_uint(ap[4]);
                a[i][3] = __float_as_uint(ap[8 * WSTR + 4]);
            }
            #pragma unroll
            for (int j = 0; j < 4; j++) {
                const float* bp = &Wb[(n0w + 8 * j + gid) * WSTR + kk];
                unsigned b0 = __float_as_uint(bp[0]), b1 = __float_as_uint(bp[4]);
                mma8(acc[0][j], a[0][0], a[0][1], a[0][2], a[0][3], b0, b1);
                mma8(acc[1][j], a[1][0], a[1][1], a[1][2], a[1][3], b0, b1);
            }
        }
    }

    // epilogue: +bias -> Res (fp32)
    #pragma unroll
    for (int j = 0; j < 4; j++) {
        int c0 = n0w + 8 * j + 2 * tig;
        float b0 = __ldg(&qkv_b[wbase + c0]);
        float b1 = __ldg(&qkv_b[wbase + c0 + 1]);
        #pragma unroll
        for (int i = 0; i < 2; i++) {
            int r = m0w + 16 * i + gid;
            Res[r * 68 + c0]           = acc[i][j][0] + b0;
            Res[r * 68 + c0 + 1]       = acc[i][j][1] + b1;
            Res[(r + 8) * 68 + c0]     = acc[i][j][2] + b0;
            Res[(r + 8) * 68 + c0 + 1] = acc[i][j][3] + b1;
        }
    }
    __syncthreads();

    // LN on k (cols 0..31) and v (cols 32..63); ddof=1, denom = std + eps
    {
        int p = tid & 127;
        int which = tid >> 7;
        int base = which ? 32 : 0;
        const float* lw = which ? vlw : klw;
        const float* lb = which ? vlb : klb;
        float s = 0.f, s2 = 0.f;
        #pragma unroll
        for (int c = 0; c < 32; c++) {
            float v = Res[p * 68 + base + c];
            s += v; s2 += v * v;
        }
        float mean = s * (1.f / 32.f);
        float var = (s2 - s * mean) * (1.f / 31.f);
        var = fmaxf(var, 0.f);
        float inv = 1.f / (sqrtf(var) + EPS);
        #pragma unroll
        for (int c = 0; c < 32; c++) {
            float v = Res[p * 68 + base + c];
            Res[p * 68 + base + c] =
                __ldg(&lw[head * 32 + c]) * ((v - mean) * inv) + __ldg(&lb[head * 32 + c]);
        }
    }
    __syncthreads();

    // kv outer product (fp32 exact)
    {
        int d  = tid >> 3;
        int e0 = (tid & 7) << 2;
        float a0 = 0.f, a1 = 0.f, a2 = 0.f, a3 = 0.f;
        for (int p = 0; p < TM; p++) {
            float kd = Res[p * 68 + d];
            a0 += kd * Res[p * 68 + 32 + e0 + 0];
            a1 += kd * Res[p * 68 + 32 + e0 + 1];
            a2 += kd * Res[p * 68 + 32 + e0 + 2];
            a3 += kd * Res[p * 68 + 32 + e0 + 3];
        }
        int bi = m0 / NN;
        float* dst = &g_kv[(((size_t)bi * HEADS + head) * HEADC + d) * HEADC + e0];
        const float sc = 1.f / (float)NN;
        atomicAdd(dst + 0, a0 * sc);
        atomicAdd(dst + 1, a1 * sc);
        atomicAdd(dst + 2, a2 * sc);
        atomicAdd(dst + 3, a3 * sc);
    }
}

// ---------------------------------------------------------------------------
// Kernel 2: q proj -> attn (q@kv) + residual -> GELU MLP, all TF32 mma.
// 512 threads, warp grid 4(M) x 4(N, 48 cols each). tf32 bits pre-staged.
// grid: MTOT/TM, smem: A[128][196] + Bs[128][196] + Wc[2*192*20] = 231,424 B
// ---------------------------------------------------------------------------
__global__ __launch_bounds__(512) void k2_attn_mlp(
    const float* __restrict__ x,
    const float* __restrict__ qkv_w, const float* __restrict__ qkv_b,
    const float* __restrict__ o1w, const float* __restrict__ o1b,
    const float* __restrict__ o2w, const float* __restrict__ o2b,
    float* __restrict__ out)
{
    extern __shared__ float sm[];
    float* A  = sm;                       // 128*196
    float* Bs = sm + 128 * ASTR;          // 128*196
    float* Wc = sm + 2 * 128 * ASTR;      // 2*192*20; doubles as kvT[192][36]

    const int tid = threadIdx.x;
    const int m0  = blockIdx.x * TM;
    const int bi  = m0 / NN;
    const int warp = tid >> 5, lane = tid & 31;
    const int gid = lane >> 2, tig = lane & 3;
    const int m0w = (warp >> 2) * 32, n0w = (warp & 3) * 48;

    // branchless index for the second 256-wide W-staging pass:
    // threads 256..511 redo element (idx-512) harmlessly instead of predicating.
    const int idx2 = (tid + 512 < 768) ? (tid + 512) : (tid + 512 - 256);

    // stage 0: x -> A (tf32 bits)
    for (int idx = tid; idx < TM * CC / 4; idx += 512) {
        int p = idx / 48, c4 = (idx % 48) * 4;
        float4 xv = *(const float4*)&x[(size_t)(m0 + p) * CC + c4];
        float* dst = &A[p * ASTR + c4];
        dst[0] = f2tff(xv.x); dst[1] = f2tff(xv.y);
        dst[2] = f2tff(xv.z); dst[3] = f2tff(xv.w);
    }
    __syncthreads();

    float4 wr[2];
    float acc[2][6][4];

    auto zeroacc = [&]() {
        #pragma unroll
        for (int i = 0; i < 2; i++)
            #pragma unroll
            for (int j = 0; j < 6; j++)
                #pragma unroll
                for (int e = 0; e < 4; e++) acc[i][j][e] = 0.f;
    };
    auto ldgW = [&](const float* W, int k0) {
        {
            int d = tid >> 2, kk = (tid & 3) << 2;
            wr[0] = *(const float4*)&W[(size_t)d * CC + k0 + kk];
        }
        {
            int d = idx2 >> 2, kk = (idx2 & 3) << 2;
            wr[1] = *(const float4*)&W[(size_t)d * CC + k0 + kk];
        }
    };
    auto ldgWq = [&](int k0) {
        {
            int d = tid >> 2, kk = (tid & 3) << 2;
            int grow = (d >> 5) * 96 + (d & 31);
            wr[0] = *(const float4*)&qkv_w[(size_t)grow * CC + k0 + kk];
        }
        {
            int d = idx2 >> 2, kk = (idx2 & 3) << 2;
            int grow = (d >> 5) * 96 + (d & 31);
            wr[1] = *(const float4*)&qkv_w[(size_t)grow * CC + k0 + kk];
        }
    };
    auto stsW = [&](int buf) {
        {
            int d = tid >> 2, kk = (tid & 3) << 2;
            float* dst = &Wc[buf * (192 * WSTR) + d * WSTR + kk];
            dst[0] = f2tff(wr[0].x); dst[1] = f2tff(wr[0].y);
            dst[2] = f2tff(wr[0].z); dst[3] = f2tff(wr[0].w);
        }
        {
            int d = idx2 >> 2, kk = (idx2 & 3) << 2;
            float* dst = &Wc[buf * (192 * WSTR) + d * WSTR + kk];
            dst[0] = f2tff(wr[1].x); dst[1] = f2tff(wr[1].y);
            dst[2] = f2tff(wr[1].z); dst[3] = f2tff(wr[1].w);
        }
    };
    auto mmachunk = [&](const float* Asrc, int k0, int buf) {
        const float* Wb = &Wc[buf * (192 * WSTR)];
        #pragma unroll
        for (int s = 0; s < 2; s++) {
            int kk = k0 + 8 * s + tig;
            unsigned a[2][4];
            #pragma unroll
            for (int i = 0; i < 2; i++) {
                const float* ap = &Asrc[(m0w + 16 * i + gid) * ASTR + kk];
                a[i][0] = __float_as_uint(ap[0]);
                a[i][1] = __float_as_uint(ap[8 * ASTR]);
                a[i][2] = __float_as_uint(ap[4]);
                a[i][3] = __float_as_uint(ap[8 * ASTR + 4]);
            }
            #pragma unroll
            for (int j = 0; j < 6; j++) {
                const float* bp = &Wb[(n0w + 8 * j + gid) * WSTR + 8 * s + tig];
                unsigned b0 = __float_as_uint(bp[0]), b1 = __float_as_uint(bp[4]);
                mma8(acc[0][j], a[0][0], a[0][1], a[0][2], a[0][3], b0, b1);
                mma8(acc[1][j], a[1][0], a[1][1], a[1][2], a[1][3], b0, b1);
            }
        }
    };

    // ---------------- q projection: Bs = A @ Wq^T + bq (tf32 bits) ----------------
    zeroacc();
    ldgWq(0);
    #pragma unroll 1
    for (int c = 0; c < 12; c++) {
        stsW(c & 1);
        if (c < 11) ldgWq((c + 1) * 16);
        __syncthreads();
        mmachunk(A, c * 16, c & 1);
    }
    #pragma unroll
    for (int j = 0; j < 6; j++) {
        int c0 = n0w + 8 * j + 2 * tig;
        float b0 = __ldg(&qkv_b[(c0 >> 5) * 96 + (c0 & 31)]);
        float b1 = __ldg(&qkv_b[((c0 + 1) >> 5) * 96 + ((c0 + 1) & 31)]);
        #pragma unroll
        for (int i = 0; i < 2; i++) {
            int r = m0w + 16 * i + gid;
            Bs[r * ASTR + c0]           = f2tff(acc[i][j][0] + b0);
            Bs[r * ASTR + c0 + 1]       = f2tff(acc[i][j][1] + b1);
            Bs[(r + 8) * ASTR + c0]     = f2tff(acc[i][j][2] + b0);
            Bs[(r + 8) * ASTR + c0 + 1] = f2tff(acc[i][j][3] + b1);
        }
    }
    __syncthreads();

    // ---------------- stage kv transposed (tf32 bits): kvT[(h*32+e)][d] ----------------
    for (int idx = tid; idx < HEADS * HEADC * HEADC; idx += 512) {
        int hd = idx >> 5, e = idx & 31;
        int h = hd >> 5, d = hd & 31;
        Wc[(h * 32 + e) * KVSTR + d] =
            f2tff(g_kv[(size_t)bi * HEADS * HEADC * HEADC + idx]);
    }
    __syncthreads();

    // ---------------- attn: A = x + q @ kv (block-diag per head) ----------------
    {
        // init acc from A (holds tf32(x))
        #pragma unroll
        for (int j = 0; j < 6; j++) {
            int c0 = n0w + 8 * j + 2 * tig;
            #pragma unroll
            for (int i = 0; i < 2; i++) {
                int r = m0w + 16 * i + gid;
                acc[i][j][0] = A[r * ASTR + c0];
                acc[i][j][1] = A[r * ASTR + c0 + 1];
                acc[i][j][2] = A[(r + 8) * ASTR + c0];
                acc[i][j][3] = A[(r + 8) * ASTR + c0 + 1];
            }
        }
        const int h_lo = n0w >> 5;                // this warp's 48 cols span 2 heads
        #pragma unroll
        for (int s = 0; s < 4; s++) {
            unsigned qa[2][2][4];
            #pragma unroll
            for (int hh = 0; hh < 2; hh++) {
                int cb = (h_lo + hh) * 32 + 8 * s + tig;
                #pragma unroll
                for (int i = 0; i < 2; i++) {
                    const float* qp = &Bs[(m0w + 16 * i + gid) * ASTR + cb];
                    qa[hh][i][0] = __float_as_uint(qp[0]);
                    qa[hh][i][1] = __float_as_uint(qp[8 * ASTR]);
                    qa[hh][i][2] = __float_as_uint(qp[4]);
                    qa[hh][i][3] = __float_as_uint(qp[8 * ASTR + 4]);
                }
            }
            #pragma unroll
            for (int j = 0; j < 6; j++) {
                int hh = (((n0w + 8 * j) >> 5) != h_lo) ? 1 : 0;
                const float* bp = &Wc[(n0w + 8 * j + gid) * KVSTR + 8 * s + tig];
                unsigned b0 = __float_as_uint(bp[0]), b1 = __float_as_uint(bp[4]);
                mma8(acc[0][j], qa[hh][0][0], qa[hh][0][1], qa[hh][0][2], qa[hh][0][3], b0, b1);
                mma8(acc[1][j], qa[hh][1][0], qa[hh][1][1], qa[hh][1][2], qa[hh][1][3], b0, b1);
            }
        }
        // ret -> A as tf32 bits (only consumed by GEMM1)
        #pragma unroll
        for (int j = 0; j < 6; j++) {
            int c0 = n0w + 8 * j + 2 * tig;
            #pragma unroll
            for (int i = 0; i < 2; i++) {
                int r = m0w + 16 * i + gid;
                A[r * ASTR + c0]           = f2tff(acc[i][j][0]);
                A[r * ASTR + c0 + 1]       = f2tff(acc[i][j][1]);
                A[(r + 8) * ASTR + c0]     = f2tff(acc[i][j][2]);
                A[(r + 8) * ASTR + c0 + 1] = f2tff(acc[i][j][3]);
            }
        }
    }
    __syncthreads();

    // ---------------- GEMM1: Bs = gelu(A @ o1w^T + o1b) (tf32 bits) ----------------
    zeroacc();
    ldgW(o1w, 0);
    #pragma unroll 1
    for (int c = 0; c < 12; c++) {
        stsW(c & 1);
        if (c < 11) ldgW(o1w, (c + 1) * 16);
        __syncthreads();
        mmachunk(A, c * 16, c & 1);
    }
    #pragma unroll
    for (int j = 0; j < 6; j++) {
        int c0 = n0w + 8 * j + 2 * tig;
        float b0 = __ldg(&o1b[c0]);
        float b1 = __ldg(&o1b[c0 + 1]);
        #pragma unroll
        for (int i = 0; i < 2; i++) {
            int r = m0w + 16 * i + gid;
            float t0 = acc[i][j][0] + b0;
            float t1 = acc[i][j][1] + b1;
            float t2 = acc[i][j][2] + b0;
            float t3 = acc[i][j][3] + b1;
            Bs[r * ASTR + c0]           = f2tff(0.5f * t0 * (1.f + erff(t0 * 0.70710678118654752f)));
            Bs[r * ASTR + c0 + 1]       = f2tff(0.5f * t1 * (1.f + erff(t1 * 0.70710678118654752f)));
            Bs[(r + 8) * ASTR + c0]     = f2tff(0.5f * t2 * (1.f + erff(t2 * 0.70710678118654752f)));
            Bs[(r + 8) * ASTR + c0 + 1] = f2tff(0.5f * t3 * (1.f + erff(t3 * 0.70710678118654752f)));
        }
    }

    // ---------------- GEMM2: out = Bs @ o2w^T + o2b + x ----------------
    zeroacc();
    ldgW(o2w, 0);
    #pragma unroll 1
    for (int c = 0; c < 12; c++) {
        stsW(c & 1);
        if (c < 11) ldgW(o2w, (c + 1) * 16);
        __syncthreads();
        mmachunk(Bs, c * 16, c & 1);
    }
    // raw fp32 acc -> A, then coalesced epilogue store
    #pragma unroll
    for (int j = 0; j < 6; j++) {
        int c0 = n0w + 8 * j + 2 * tig;
        #pragma unroll
        for (int i = 0; i < 2; i++) {
            int r = m0w + 16 * i + gid;
            A[r * ASTR + c0]           = acc[i][j][0];
            A[r * ASTR + c0 + 1]       = acc[i][j][1];
            A[(r + 8) * ASTR + c0]     = acc[i][j][2];
            A[(r + 8) * ASTR + c0 + 1] = acc[i][j][3];
        }
    }
    __syncthreads();
    for (int idx = tid; idx < TM * CC / 4; idx += 512) {
        int p = idx / 48, c4 = (idx % 48) * 4;
        float4 av = *(float4*)&A[p * ASTR + c4];
        float4 bv = *(const float4*)&o2b[c4];
        float4 xv = *(const float4*)&x[(size_t)(m0 + p) * CC + c4];
        av.x += bv.x + xv.x;
        av.y += bv.y + xv.y;
        av.z += bv.z + xv.z;
        av.w += bv.w + xv.w;
        *(float4*)&out[(size_t)(m0 + p) * CC + c4] = av;
    }
}

// ---------------------------------------------------------------------------

extern "C" void kernel_launch(void* const* d_in, const int* in_sizes, int n_in,
                              void* d_out, int out_size)
{
    const float* x     = (const float*)d_in[0];
    const float* qkv_w = (const float*)d_in[1];
    const float* qkv_b = (const float*)d_in[2];
    const float* o1w   = (const float*)d_in[3];
    const float* o1b   = (const float*)d_in[4];
    const float* o2w   = (const float*)d_in[5];
    const float* o2b   = (const float*)d_in[6];
    const float* klw   = (const float*)d_in[7];
    const float* klb   = (const float*)d_in[8];
    const float* vlw   = (const float*)d_in[9];
    const float* vlb   = (const float*)d_in[10];
    float* out = (float*)d_out;

    const int smem1 = (2 * 128 * WSTR + 2 * 64 * WSTR + 128 * 68) * 4;   // 65,536 B
    const int smem2 = (2 * 128 * ASTR + 2 * 192 * WSTR) * 4;             // 231,424 B
    cudaFuncSetAttribute(k1_kv, cudaFuncAttributeMaxDynamicSharedMemorySize, smem1);
    cudaFuncSetAttribute(k2_attn_mlp, cudaFuncAttributeMaxDynamicSharedMemorySize, smem2);

    zero_kv_kernel<<<(BB * HEADS * HEADC * HEADC + 255) / 256, 256>>>();

    dim3 g1(HEADS, MTOT / TM);
    k1_kv<<<g1, 256, smem1>>>(x, qkv_w, qkv_b, klw, klb, vlw, vlb);

    k2_attn_mlp<<<MTOT / TM, 512, smem2>>>(x, qkv_w, qkv_b, o1w, o1b, o2w, o2b, out);
}

// round 12
// speedup vs baseline: 1.0984x; 1.0984x over previous
#include <cuda_runtime.h>
#include <math.h>

#define BB 4
#define NN 65536
#define CC 192
#define HEADS 6
#define HEADC 32
#define MTOT (BB*NN)
#define TM 128
#define EPS 1e-5f
#define ASTR 196
#define WSTR 20
#define KVSTR 36

// only device-global scratch: tiny kv accumulator
__device__ float g_kv[BB * HEADS * HEADC * HEADC];

__global__ void zero_kv_kernel() {
    int i = blockIdx.x * blockDim.x + threadIdx.x;
    if (i < BB * HEADS * HEADC * HEADC) g_kv[i] = 0.f;
}

__device__ __forceinline__ unsigned f2tfu(float f) {
    unsigned u;
    asm("cvt.rna.tf32.f32 %0, %1;" : "=r"(u) : "f"(f));
    return u;
}
__device__ __forceinline__ float f2tff(float f) {     // tf32-truncated, as float bits
    return __uint_as_float(f2tfu(f));
}

__device__ __forceinline__ void mma8(float* c,
    unsigned a0, unsigned a1, unsigned a2, unsigned a3,
    unsigned b0, unsigned b1)
{
    asm volatile(
        "mma.sync.aligned.m16n8k8.row.col.f32.tf32.tf32.f32 "
        "{%0,%1,%2,%3}, {%4,%5,%6,%7}, {%8,%9}, {%0,%1,%2,%3};"
        : "+f"(c[0]), "+f"(c[1]), "+f"(c[2]), "+f"(c[3])
        : "r"(a0), "r"(a1), "r"(a2), "r"(a3), "r"(b0), "r"(b1));
}

// ---------------------------------------------------------------------------
// Kernel 1: k,v projection (one head per block) via TF32 mma, LN(k), LN(v),
// kv outer-product accumulation. All smem operands pre-converted to tf32 bits.
// grid: (HEADS, MTOT/TM), block: 256
// smem: As[2][128][20] + Wk[2][64][20] + Res[128][68] = 65,536 B
// ---------------------------------------------------------------------------
__global__ __launch_bounds__(256) void k1_kv(
    const float* __restrict__ x, const float* __restrict__ qkv_w,
    const float* __restrict__ qkv_b,
    const float* __restrict__ klw, const float* __restrict__ klb,
    const float* __restrict__ vlw, const float* __restrict__ vlb)
{
    extern __shared__ float sm[];
    float* As  = sm;                                   // 2*128*20
    float* Wk  = sm + 2 * 128 * WSTR;                  // 2*64*20
    float* Res = sm + 2 * 128 * WSTR + 2 * 64 * WSTR;  // 128*68

    const int tid  = threadIdx.x;
    const int head = blockIdx.x;
    const int m0   = blockIdx.y * TM;
    const int wbase = head * 96 + 32;              // k rows, then v rows

    const int warp = tid >> 5, lane = tid & 31;
    const int gid = lane >> 2, tig = lane & 3;
    const int m0w = (warp >> 1) * 32, n0w = (warp & 1) * 32;

    float4 xr[2], wreg;

    float acc[2][4][4];
    #pragma unroll
    for (int i = 0; i < 2; i++)
        #pragma unroll
        for (int j = 0; j < 4; j++)
            #pragma unroll
            for (int e = 0; e < 4; e++) acc[i][j][e] = 0.f;

    // prefetch chunk 0
    {
        #pragma unroll
        for (int t = 0; t < 2; t++) {
            int idx = tid + t * 256, p = idx >> 2, kk = (idx & 3) << 2;
            xr[t] = *(const float4*)&x[(size_t)(m0 + p) * CC + kk];
        }
        int d = tid >> 2, kk = (tid & 3) << 2;
        wreg = *(const float4*)&qkv_w[(size_t)(wbase + d) * CC + kk];
    }

    #pragma unroll 1
    for (int c = 0; c < 12; c++) {
        // STS chunk c (convert to tf32 bits once here)
        {
            #pragma unroll
            for (int t = 0; t < 2; t++) {
                int idx = tid + t * 256, p = idx >> 2, kk = (idx & 3) << 2;
                float* dst = &As[(c & 1) * 128 * WSTR + p * WSTR + kk];
                dst[0] = f2tff(xr[t].x); dst[1] = f2tff(xr[t].y);
                dst[2] = f2tff(xr[t].z); dst[3] = f2tff(xr[t].w);
            }
            int d = tid >> 2, kk = (tid & 3) << 2;
            float* dst = &Wk[(c & 1) * 64 * WSTR + d * WSTR + kk];
            dst[0] = f2tff(wreg.x); dst[1] = f2tff(wreg.y);
            dst[2] = f2tff(wreg.z); dst[3] = f2tff(wreg.w);
        }
        // LDG chunk c+1
        if (c < 11) {
            int k0 = (c + 1) * 16;
            #pragma unroll
            for (int t = 0; t < 2; t++) {
                int idx = tid + t * 256, p = idx >> 2, kk = (idx & 3) << 2;
                xr[t] = *(const float4*)&x[(size_t)(m0 + p) * CC + k0 + kk];
            }
            int d = tid >> 2, kk = (tid & 3) << 2;
            wreg = *(const float4*)&qkv_w[(size_t)(wbase + d) * CC + k0 + kk];
        }
        __syncthreads();
        const float* Ab = &As[(c & 1) * 128 * WSTR];
        const float* Wb = &Wk[(c & 1) * 64 * WSTR];
        #pragma unroll
        for (int s = 0; s < 2; s++) {
            int kk = 8 * s + tig;
            unsigned a[2][4];
            #pragma unroll
            for (int i = 0; i < 2; i++) {
                const float* ap = &Ab[(m0w + 16 * i + gid) * WSTR + kk];
                a[i][0] = __float_as_uint(ap[0]);
                a[i][1] = __float_as_uint(ap[8 * WSTR]);
                a[i][2] = __float_as_uint(ap[4]);
                a[i][3] = __float_as_uint(ap[8 * WSTR + 4]);
            }
            #pragma unroll
            for (int j = 0; j < 4; j++) {
                const float* bp = &Wb[(n0w + 8 * j + gid) * WSTR + kk];
                unsigned b0 = __float_as_uint(bp[0]), b1 = __float_as_uint(bp[4]);
                mma8(acc[0][j], a[0][0], a[0][1], a[0][2], a[0][3], b0, b1);
                mma8(acc[1][j], a[1][0], a[1][1], a[1][2], a[1][3], b0, b1);
            }
        }
    }

    // epilogue: +bias -> Res (fp32)
    #pragma unroll
    for (int j = 0; j < 4; j++) {
        int c0 = n0w + 8 * j + 2 * tig;
        float b0 = __ldg(&qkv_b[wbase + c0]);
        float b1 = __ldg(&qkv_b[wbase + c0 + 1]);
        #pragma unroll
        for (int i = 0; i < 2; i++) {
            int r = m0w + 16 * i + gid;
            Res[r * 68 + c0]           = acc[i][j][0] + b0;
            Res[r * 68 + c0 + 1]       = acc[i][j][1] + b1;
            Res[(r + 8) * 68 + c0]     = acc[i][j][2] + b0;
            Res[(r + 8) * 68 + c0 + 1] = acc[i][j][3] + b1;
        }
    }
    __syncthreads();

    // LN on k (cols 0..31) and v (cols 32..63); ddof=1, denom = std + eps
    {
        int p = tid & 127;
        int which = tid >> 7;
        int base = which ? 32 : 0;
        const float* lw = which ? vlw : klw;
        const float* lb = which ? vlb : klb;
        float s = 0.f, s2 = 0.f;
        #pragma unroll
        for (int c = 0; c < 32; c++) {
            float v = Res[p * 68 + base + c];
            s += v; s2 += v * v;
        }
        float mean = s * (1.f / 32.f);
        float var = (s2 - s * mean) * (1.f / 31.f);
        var = fmaxf(var, 0.f);
        float inv = 1.f / (sqrtf(var) + EPS);
        #pragma unroll
        for (int c = 0; c < 32; c++) {
            float v = Res[p * 68 + base + c];
            Res[p * 68 + base + c] =
                __ldg(&lw[head * 32 + c]) * ((v - mean) * inv) + __ldg(&lb[head * 32 + c]);
        }
    }
    __syncthreads();

    // kv outer product (fp32 exact)
    {
        int d  = tid >> 3;
        int e0 = (tid & 7) << 2;
        float a0 = 0.f, a1 = 0.f, a2 = 0.f, a3 = 0.f;
        for (int p = 0; p < TM; p++) {
            float kd = Res[p * 68 + d];
            a0 += kd * Res[p * 68 + 32 + e0 + 0];
            a1 += kd * Res[p * 68 + 32 + e0 + 1];
            a2 += kd * Res[p * 68 + 32 + e0 + 2];
            a3 += kd * Res[p * 68 + 32 + e0 + 3];
        }
        int bi = m0 / NN;
        float* dst = &g_kv[(((size_t)bi * HEADS + head) * HEADC + d) * HEADC + e0];
        const float sc = 1.f / (float)NN;
        atomicAdd(dst + 0, a0 * sc);
        atomicAdd(dst + 1, a1 * sc);
        atomicAdd(dst + 2, a2 * sc);
        atomicAdd(dst + 3, a3 * sc);
    }
}

// ---------------------------------------------------------------------------
// Kernel 2: q proj -> attn (q@kv) + residual -> GELU MLP, all TF32 mma.
// 256 threads, warp grid 2(M) x 2(N, 96 cols each) — R7's measured-best shape,
// now with tf32 bits pre-staged (no cvt in MMA loops).
// grid: MTOT/TM, smem: A[128][196] + Bs[128][196] + Wc[2*192*20] = 231,424 B
// ---------------------------------------------------------------------------
__global__ __launch_bounds__(256) void k2_attn_mlp(
    const float* __restrict__ x,
    const float* __restrict__ qkv_w, const float* __restrict__ qkv_b,
    const float* __restrict__ o1w, const float* __restrict__ o1b,
    const float* __restrict__ o2w, const float* __restrict__ o2b,
    float* __restrict__ out)
{
    extern __shared__ float sm[];
    float* A  = sm;                       // 128*196
    float* Bs = sm + 128 * ASTR;          // 128*196
    float* Wc = sm + 2 * 128 * ASTR;      // 2*192*20; doubles as kvT[192][36]

    const int tid = threadIdx.x;
    const int m0  = blockIdx.x * TM;
    const int bi  = m0 / NN;
    const int warp = tid >> 5, lane = tid & 31;
    const int gid = lane >> 2, tig = lane & 3;
    const int m0w = (warp >> 1) * 32, n0w = (warp & 1) * 96;

    // stage 0: x -> A (tf32 bits)
    for (int idx = tid; idx < TM * CC / 4; idx += 256) {
        int p = idx / 48, c4 = (idx % 48) * 4;
        float4 xv = *(const float4*)&x[(size_t)(m0 + p) * CC + c4];
        float* dst = &A[p * ASTR + c4];
        dst[0] = f2tff(xv.x); dst[1] = f2tff(xv.y);
        dst[2] = f2tff(xv.z); dst[3] = f2tff(xv.w);
    }
    __syncthreads();

    float4 wr[3];
    float acc[2][12][4];

    auto zeroacc = [&]() {
        #pragma unroll
        for (int i = 0; i < 2; i++)
            #pragma unroll
            for (int j = 0; j < 12; j++)
                #pragma unroll
                for (int e = 0; e < 4; e++) acc[i][j][e] = 0.f;
    };
    auto ldgW = [&](const float* W, int k0) {
        #pragma unroll
        for (int t = 0; t < 3; t++) {
            int idx = tid + t * 256, d = idx >> 2, kk = (idx & 3) << 2;
            wr[t] = *(const float4*)&W[(size_t)d * CC + k0 + kk];
        }
    };
    auto ldgWq = [&](int k0) {
        #pragma unroll
        for (int t = 0; t < 3; t++) {
            int idx = tid + t * 256, d = idx >> 2, kk = (idx & 3) << 2;
            int grow = (d >> 5) * 96 + (d & 31);   // q rows of head d>>5
            wr[t] = *(const float4*)&qkv_w[(size_t)grow * CC + k0 + kk];
        }
    };
    auto stsW = [&](int buf) {
        #pragma unroll
        for (int t = 0; t < 3; t++) {
            int idx = tid + t * 256, d = idx >> 2, kk = (idx & 3) << 2;
            float* dst = &Wc[buf * (192 * WSTR) + d * WSTR + kk];
            dst[0] = f2tff(wr[t].x); dst[1] = f2tff(wr[t].y);
            dst[2] = f2tff(wr[t].z); dst[3] = f2tff(wr[t].w);
        }
    };
    auto mmachunk = [&](const float* Asrc, int k0, int buf) {
        const float* Wb = &Wc[buf * (192 * WSTR)];
        #pragma unroll
        for (int s = 0; s < 2; s++) {
            int kk = k0 + 8 * s + tig;
            unsigned a[2][4];
            #pragma unroll
            for (int i = 0; i < 2; i++) {
                const float* ap = &Asrc[(m0w + 16 * i + gid) * ASTR + kk];
                a[i][0] = __float_as_uint(ap[0]);
                a[i][1] = __float_as_uint(ap[8 * ASTR]);
                a[i][2] = __float_as_uint(ap[4]);
                a[i][3] = __float_as_uint(ap[8 * ASTR + 4]);
            }
            #pragma unroll
            for (int j = 0; j < 12; j++) {
                const float* bp = &Wb[(n0w + 8 * j + gid) * WSTR + 8 * s + tig];
                unsigned b0 = __float_as_uint(bp[0]), b1 = __float_as_uint(bp[4]);
                mma8(acc[0][j], a[0][0], a[0][1], a[0][2], a[0][3], b0, b1);
                mma8(acc[1][j], a[1][0], a[1][1], a[1][2], a[1][3], b0, b1);
            }
        }
    };

    // ---------------- q projection: Bs = A @ Wq^T + bq (tf32 bits) ----------------
    zeroacc();
    ldgWq(0);
    #pragma unroll 1
    for (int c = 0; c < 12; c++) {
        stsW(c & 1);
        if (c < 11) ldgWq((c + 1) * 16);
        __syncthreads();
        mmachunk(A, c * 16, c & 1);
    }
    #pragma unroll
    for (int j = 0; j < 12; j++) {
        int c0 = n0w + 8 * j + 2 * tig;
        float b0 = __ldg(&qkv_b[(c0 >> 5) * 96 + (c0 & 31)]);
        float b1 = __ldg(&qkv_b[(c0 >> 5) * 96 + (c0 & 31) + 1]);
        #pragma unroll
        for (int i = 0; i < 2; i++) {
            int r = m0w + 16 * i + gid;
            Bs[r * ASTR + c0]           = f2tff(acc[i][j][0] + b0);
            Bs[r * ASTR + c0 + 1]       = f2tff(acc[i][j][1] + b1);
            Bs[(r + 8) * ASTR + c0]     = f2tff(acc[i][j][2] + b0);
            Bs[(r + 8) * ASTR + c0 + 1] = f2tff(acc[i][j][3] + b1);
        }
    }
    __syncthreads();   // all warps done with Wc before kvT staging

    // ---------------- stage kv transposed (tf32 bits): kvT[(h*32+e)][d] ----------------
    for (int idx = tid; idx < HEADS * HEADC * HEADC; idx += 256) {
        int hd = idx >> 5, e = idx & 31;
        int h = hd >> 5, d = hd & 31;
        Wc[(h * 32 + e) * KVSTR + d] =
            f2tff(g_kv[(size_t)bi * HEADS * HEADC * HEADC + idx]);
    }
    __syncthreads();

    // ---------------- attn: A = x + q @ kv (block-diag per head) ----------------
    {
        // init acc from A (holds tf32(x)); final residual re-adds exact x at store
        #pragma unroll
        for (int j = 0; j < 12; j++) {
            int c0 = n0w + 8 * j + 2 * tig;
            #pragma unroll
            for (int i = 0; i < 2; i++) {
                int r = m0w + 16 * i + gid;
                acc[i][j][0] = A[r * ASTR + c0];
                acc[i][j][1] = A[r * ASTR + c0 + 1];
                acc[i][j][2] = A[(r + 8) * ASTR + c0];
                acc[i][j][3] = A[(r + 8) * ASTR + c0 + 1];
            }
        }
        const int h0 = n0w >> 5;   // first of this warp's 3 heads
        #pragma unroll
        for (int s = 0; s < 4; s++) {
            unsigned qa[3][2][4];
            #pragma unroll
            for (int hh = 0; hh < 3; hh++) {
                int cb = (h0 + hh) * 32 + 8 * s + tig;
                #pragma unroll
                for (int i = 0; i < 2; i++) {
                    const float* qp = &Bs[(m0w + 16 * i + gid) * ASTR + cb];
                    qa[hh][i][0] = __float_as_uint(qp[0]);
                    qa[hh][i][1] = __float_as_uint(qp[8 * ASTR]);
                    qa[hh][i][2] = __float_as_uint(qp[4]);
                    qa[hh][i][3] = __float_as_uint(qp[8 * ASTR + 4]);
                }
            }
            #pragma unroll
            for (int j = 0; j < 12; j++) {
                int hh = j >> 2;
                const float* bp = &Wc[(n0w + 8 * j + gid) * KVSTR + 8 * s + tig];
                unsigned b0 = __float_as_uint(bp[0]), b1 = __float_as_uint(bp[4]);
                mma8(acc[0][j], qa[hh][0][0], qa[hh][0][1], qa[hh][0][2], qa[hh][0][3], b0, b1);
                mma8(acc[1][j], qa[hh][1][0], qa[hh][1][1], qa[hh][1][2], qa[hh][1][3], b0, b1);
            }
        }
        // ret -> A as tf32 bits (only consumed by GEMM1)
        #pragma unroll
        for (int j = 0; j < 12; j++) {
            int c0 = n0w + 8 * j + 2 * tig;
            #pragma unroll
            for (int i = 0; i < 2; i++) {
                int r = m0w + 16 * i + gid;
                A[r * ASTR + c0]           = f2tff(acc[i][j][0]);
                A[r * ASTR + c0 + 1]       = f2tff(acc[i][j][1]);
                A[(r + 8) * ASTR + c0]     = f2tff(acc[i][j][2]);
                A[(r + 8) * ASTR + c0 + 1] = f2tff(acc[i][j][3]);
            }
        }
    }
    __syncthreads();   // ret visible to all; kvT free

    // ---------------- GEMM1: Bs = gelu(A @ o1w^T + o1b) (tf32 bits) ----------------
    zeroacc();
    ldgW(o1w, 0);
    #pragma unroll 1
    for (int c = 0; c < 12; c++) {
        stsW(c & 1);
        if (c < 11) ldgW(o1w, (c + 1) * 16);
        __syncthreads();
        mmachunk(A, c * 16, c & 1);
    }
    #pragma unroll
    for (int j = 0; j < 12; j++) {
        int c0 = n0w + 8 * j + 2 * tig;
        float b0 = __ldg(&o1b[c0]);
        float b1 = __ldg(&o1b[c0 + 1]);
        #pragma unroll
        for (int i = 0; i < 2; i++) {
            int r = m0w + 16 * i + gid;
            float t0 = acc[i][j][0] + b0;
            float t1 = acc[i][j][1] + b1;
            float t2 = acc[i][j][2] + b0;
            float t3 = acc[i][j][3] + b1;
            Bs[r * ASTR + c0]           = f2tff(0.5f * t0 * (1.f + erff(t0 * 0.70710678118654752f)));
            Bs[r * ASTR + c0 + 1]       = f2tff(0.5f * t1 * (1.f + erff(t1 * 0.70710678118654752f)));
            Bs[(r + 8) * ASTR + c0]     = f2tff(0.5f * t2 * (1.f + erff(t2 * 0.70710678118654752f)));
            Bs[(r + 8) * ASTR + c0 + 1] = f2tff(0.5f * t3 * (1.f + erff(t3 * 0.70710678118654752f)));
        }
    }

    // ---------------- GEMM2: out = Bs @ o2w^T + o2b + x ----------------
    zeroacc();
    ldgW(o2w, 0);
    #pragma unroll 1
    for (int c = 0; c < 12; c++) {
        stsW(c & 1);
        if (c < 11) ldgW(o2w, (c + 1) * 16);
        __syncthreads();
        mmachunk(Bs, c * 16, c & 1);
    }
    // raw fp32 acc -> A, then coalesced epilogue store (exact x re-added here)
    #pragma unroll
    for (int j = 0; j < 12; j++) {
        int c0 = n0w + 8 * j + 2 * tig;
        #pragma unroll
        for (int i = 0; i < 2; i++) {
            int r = m0w + 16 * i + gid;
            A[r * ASTR + c0]           = acc[i][j][0];
            A[r * ASTR + c0 + 1]       = acc[i][j][1];
            A[(r + 8) * ASTR + c0]     = acc[i][j][2];
            A[(r + 8) * ASTR + c0 + 1] = acc[i][j][3];
        }
    }
    __syncthreads();
    for (int idx = tid; idx < TM * CC / 4; idx += 256) {
        int p = idx / 48, c4 = (idx % 48) * 4;
        float4 av = *(float4*)&A[p * ASTR + c4];
        float4 bv = *(const float4*)&o2b[c4];
        float4 xv = *(const float4*)&x[(size_t)(m0 + p) * CC + c4];
        av.x += bv.x + xv.x;
        av.y += bv.y + xv.y;
        av.z += bv.z + xv.z;
        av.w += bv.w + xv.w;
        *(float4*)&out[(size_t)(m0 + p) * CC + c4] = av;
    }
}

// ---------------------------------------------------------------------------

extern "C" void kernel_launch(void* const* d_in, const int* in_sizes, int n_in,
                              void* d_out, int out_size)
{
    const float* x     = (const float*)d_in[0];
    const float* qkv_w = (const float*)d_in[1];
    const float* qkv_b = (const float*)d_in[2];
    const float* o1w   = (const float*)d_in[3];
    const float* o1b   = (const float*)d_in[4];
    const float* o2w   = (const float*)d_in[5];
    const float* o2b   = (const float*)d_in[6];
    const float* klw   = (const float*)d_in[7];
    const float* klb   = (const float*)d_in[8];
    const float* vlw   = (const float*)d_in[9];
    const float* vlb   = (const float*)d_in[10];
    float* out = (float*)d_out;

    const int smem1 = (2 * 128 * WSTR + 2 * 64 * WSTR + 128 * 68) * 4;   // 65,536 B
    const int smem2 = (2 * 128 * ASTR + 2 * 192 * WSTR) * 4;             // 231,424 B
    cudaFuncSetAttribute(k1_kv, cudaFuncAttributeMaxDynamicSharedMemorySize, smem1);
    cudaFuncSetAttribute(k2_attn_mlp, cudaFuncAttributeMaxDynamicSharedMemorySize, smem2);

    zero_kv_kernel<<<(BB * HEADS * HEADC * HEADC + 255) / 256, 256>>>();

    dim3 g1(HEADS, MTOT / TM);
    k1_kv<<<g1, 256, smem1>>>(x, qkv_w, qkv_b, klw, klb, vlw, vlb);

    k2_attn_mlp<<<MTOT / TM, 256, smem2>>>(x, qkv_w, qkv_b, o1w, o1b, o2w, o2b, out);
}

// round 15
// speedup vs baseline: 1.2699x; 1.1561x over previous
#include <cuda_runtime.h>
#include <cuda_fp16.h>
#include <math.h>
#include <cstdint>

#define BB 4
#define NN 65536
#define CC 192
#define HEADS 6
#define HEADC 32
#define MTOT (BB*NN)
#define TM 128
#define EPS 1e-5f

// only device-global scratch: tiny kv accumulator
__device__ float g_kv[BB * HEADS * HEADC * HEADC];

__global__ void zero_kv_kernel() {
    int i = blockIdx.x * blockDim.x + threadIdx.x;
    if (i < BB * HEADS * HEADC * HEADC) g_kv[i] = 0.f;
}

__device__ __forceinline__ unsigned pk2h(float a, float b) {
    __half2 h = __floats2half2_rn(a, b);
    return *reinterpret_cast<unsigned*>(&h);
}
__device__ __forceinline__ float2 up2f(unsigned w) {
    __half2 h = *reinterpret_cast<__half2*>(&w);
    return __half22float2(h);
}

__device__ __forceinline__ void mma16(float* c,
    unsigned a0, unsigned a1, unsigned a2, unsigned a3,
    unsigned b0, unsigned b1)
{
    asm volatile(
        "mma.sync.aligned.m16n8k16.row.col.f32.f16.f16.f32 "
        "{%0,%1,%2,%3}, {%4,%5,%6,%7}, {%8,%9}, {%0,%1,%2,%3};"
        : "+f"(c[0]), "+f"(c[1]), "+f"(c[2]), "+f"(c[3])
        : "r"(a0), "r"(a1), "r"(a2), "r"(a3), "r"(b0), "r"(b1));
}

// ---------------------------------------------------------------------------
// Kernel 1: k,v projection (one head per block) via fp16 mma (fp32 accum),
// LN(k), LN(v), kv outer-product accumulation.
// grid: (HEADS, MTOT/TM), block: 256
// smem: Au[2][128][20w] + Wu[2][64][20w] + Res[128][68]f = 65,536 B
// ---------------------------------------------------------------------------
__global__ __launch_bounds__(256) void k1_kv(
    const float* __restrict__ x, const float* __restrict__ qkv_w,
    const float* __restrict__ qkv_b,
    const float* __restrict__ klw, const float* __restrict__ klb,
    const float* __restrict__ vlw, const float* __restrict__ vlb)
{
    extern __shared__ float sm[];
    unsigned* Au = (unsigned*)sm;                // 2*128*20 = 5120 w
    unsigned* Wu = (unsigned*)sm + 5120;         // 2*64*20  = 2560 w
    float*    Res = sm + 5120 + 2560;            // 128*68 floats

    const int tid  = threadIdx.x;
    const int head = blockIdx.x;
    const int m0   = blockIdx.y * TM;
    const int wbase = head * 96 + 32;            // k rows, then v rows

    const int warp = tid >> 5, lane = tid & 31;
    const int gid = lane >> 2, tig = lane & 3;
    const int m0w = (warp >> 1) * 32, n0w = (warp & 1) * 32;

    const int sp   = tid >> 1;                   // staging row
    const int sseg = tid & 1;                    // 8-half segment

    float4 xr[2], wr[2];

    float acc[2][4][4];
    #pragma unroll
    for (int i = 0; i < 2; i++)
        #pragma unroll
        for (int j = 0; j < 4; j++)
            #pragma unroll
            for (int e = 0; e < 4; e++) acc[i][j][e] = 0.f;

    // prefetch chunk 0 (k = 0..15)
    {
        const float* xp = &x[(size_t)(m0 + sp) * CC + sseg * 8];
        xr[0] = *(const float4*)xp;
        xr[1] = *(const float4*)(xp + 4);
        if (tid < 128) {
            const float* wp = &qkv_w[(size_t)(wbase + sp) * CC + sseg * 8];
            wr[0] = *(const float4*)wp;
            wr[1] = *(const float4*)(wp + 4);
        }
    }

    #pragma unroll 1
    for (int c = 0; c < 12; c++) {
        // STS chunk c (fp16-pack here, once)
        {
            unsigned* da = Au + (c & 1) * 2560 + sp * 20 + sseg * 4;
            da[0] = pk2h(xr[0].x, xr[0].y);
            da[1] = pk2h(xr[0].z, xr[0].w);
            da[2] = pk2h(xr[1].x, xr[1].y);
            da[3] = pk2h(xr[1].z, xr[1].w);
            if (tid < 128) {
                unsigned* dw = Wu + (c & 1) * 1280 + sp * 20 + sseg * 4;
                dw[0] = pk2h(wr[0].x, wr[0].y);
                dw[1] = pk2h(wr[0].z, wr[0].w);
                dw[2] = pk2h(wr[1].x, wr[1].y);
                dw[3] = pk2h(wr[1].z, wr[1].w);
            }
        }
        // LDG chunk c+1
        if (c < 11) {
            int k0 = (c + 1) * 16;
            const float* xp = &x[(size_t)(m0 + sp) * CC + k0 + sseg * 8];
            xr[0] = *(const float4*)xp;
            xr[1] = *(const float4*)(xp + 4);
            if (tid < 128) {
                const float* wp = &qkv_w[(size_t)(wbase + sp) * CC + k0 + sseg * 8];
                wr[0] = *(const float4*)wp;
                wr[1] = *(const float4*)(wp + 4);
            }
        }
        __syncthreads();
        const unsigned* Ab = Au + (c & 1) * 2560;
        const unsigned* Wb = Wu + (c & 1) * 1280;
        unsigned a[2][4];
        #pragma unroll
        for (int i = 0; i < 2; i++) {
            const unsigned* ap = Ab + (m0w + 16 * i + gid) * 20 + tig;
            a[i][0] = ap[0];
            a[i][1] = ap[8 * 20];
            a[i][2] = ap[4];
            a[i][3] = ap[8 * 20 + 4];
        }
        #pragma unroll
        for (int j = 0; j < 4; j++) {
            const unsigned* bp = Wb + (n0w + 8 * j + gid) * 20 + tig;
            unsigned b0 = bp[0], b1 = bp[4];
            mma16(acc[0][j], a[0][0], a[0][1], a[0][2], a[0][3], b0, b1);
            mma16(acc[1][j], a[1][0], a[1][1], a[1][2], a[1][3], b0, b1);
        }
    }

    // epilogue: +bias -> Res (fp32)
    #pragma unroll
    for (int j = 0; j < 4; j++) {
        int c0 = n0w + 8 * j + 2 * tig;
        float b0 = __ldg(&qkv_b[wbase + c0]);
        float b1 = __ldg(&qkv_b[wbase + c0 + 1]);
        #pragma unroll
        for (int i = 0; i < 2; i++) {
            int r = m0w + 16 * i + gid;
            Res[r * 68 + c0]           = acc[i][j][0] + b0;
            Res[r * 68 + c0 + 1]       = acc[i][j][1] + b1;
            Res[(r + 8) * 68 + c0]     = acc[i][j][2] + b0;
            Res[(r + 8) * 68 + c0 + 1] = acc[i][j][3] + b1;
        }
    }
    __syncthreads();

    // LN on k (cols 0..31) and v (cols 32..63); ddof=1, denom = std + eps
    {
        int p = tid & 127;
        int which = tid >> 7;
        int base = which ? 32 : 0;
        const float* lw = which ? vlw : klw;
        const float* lb = which ? vlb : klb;
        float s = 0.f, s2 = 0.f;
        #pragma unroll
        for (int c = 0; c < 32; c++) {
            float v = Res[p * 68 + base + c];
            s += v; s2 += v * v;
        }
        float mean = s * (1.f / 32.f);
        float var = (s2 - s * mean) * (1.f / 31.f);
        var = fmaxf(var, 0.f);
        float inv = 1.f / (sqrtf(var) + EPS);
        #pragma unroll
        for (int c = 0; c < 32; c++) {
            float v = Res[p * 68 + base + c];
            Res[p * 68 + base + c] =
                __ldg(&lw[head * 32 + c]) * ((v - mean) * inv) + __ldg(&lb[head * 32 + c]);
        }
    }
    __syncthreads();

    // kv outer product (fp32 exact)
    {
        int d  = tid >> 3;
        int e0 = (tid & 7) << 2;
        float a0 = 0.f, a1 = 0.f, a2 = 0.f, a3 = 0.f;
        for (int p = 0; p < TM; p++) {
            float kd = Res[p * 68 + d];
            a0 += kd * Res[p * 68 + 32 + e0 + 0];
            a1 += kd * Res[p * 68 + 32 + e0 + 1];
            a2 += kd * Res[p * 68 + 32 + e0 + 2];
            a3 += kd * Res[p * 68 + 32 + e0 + 3];
        }
        int bi = m0 / NN;
        float* dst = &g_kv[(((size_t)bi * HEADS + head) * HEADC + d) * HEADC + e0];
        const float sc = 1.f / (float)NN;
        atomicAdd(dst + 0, a0 * sc);
        atomicAdd(dst + 1, a1 * sc);
        atomicAdd(dst + 2, a2 * sc);
        atomicAdd(dst + 3, a3 * sc);
    }
}

// ---------------------------------------------------------------------------
// Kernel 2: q proj -> attn (q@kv) + residual -> GELU MLP, all fp16 mma.
// 256 threads, warp grid 2(M) x 2(N, 96 cols each).
// smem: Au[128][100w] + Bu[128][100w] + Wu[2][192][20w] = 133,120 B
// Final fp32 stage F (stride 200 floats) overlays Au+Bu.
// ---------------------------------------------------------------------------
#define AW 100
#define K2_SMEM ((12800 + 12800 + 2 * 3840) * 4)

__global__ __launch_bounds__(256) void k2_attn_mlp(
    const float* __restrict__ x,
    const float* __restrict__ qkv_w, const float* __restrict__ qkv_b,
    const float* __restrict__ o1w, const float* __restrict__ o1b,
    const float* __restrict__ o2w, const float* __restrict__ o2b,
    float* __restrict__ out)
{
    extern __shared__ float sm[];
    unsigned* Au = (unsigned*)sm;            // 128*100 w
    unsigned* Bu = Au + 12800;               // 128*100 w
    unsigned* Wu = Bu + 12800;               // 2 * 192*20 w; also kvT
    float*    F  = sm;                       // fp32 final stage, stride 200

    const int tid = threadIdx.x;
    const int m0  = blockIdx.x * TM;
    const int bi  = m0 / NN;
    const int warp = tid >> 5, lane = tid & 31;
    const int gid = lane >> 2, tig = lane & 3;
    const int m0w = (warp >> 1) * 32, n0w = (warp & 1) * 96;
    const int h0  = n0w >> 5;

    // stage 0: x -> Au (fp16) — 24 segments of 8 floats cover all 192 channels
    for (int idx = tid; idx < TM * 24; idx += 256) {
        int p = idx / 24, seg = idx % 24;
        const float* xp = &x[(size_t)(m0 + p) * CC + seg * 8];
        float4 v0 = *(const float4*)xp;
        float4 v1 = *(const float4*)(xp + 4);
        unsigned* dst = Au + p * AW + seg * 4;
        dst[0] = pk2h(v0.x, v0.y); dst[1] = pk2h(v0.z, v0.w);
        dst[2] = pk2h(v1.x, v1.y); dst[3] = pk2h(v1.z, v1.w);
    }
    __syncthreads();

    float4 wrv[3];
    float acc[2][12][4];

    auto zeroacc = [&]() {
        #pragma unroll
        for (int i = 0; i < 2; i++)
            #pragma unroll
            for (int j = 0; j < 12; j++)
                #pragma unroll
                for (int e = 0; e < 4; e++) acc[i][j][e] = 0.f;
    };
    // W chunk: 192 rows x 16 halves (8 words), 768 quad-slots (d, seg) seg<4
    auto ldgW = [&](const float* W, int k0) {
        #pragma unroll
        for (int t = 0; t < 3; t++) {
            int idx = tid + t * 256;
            int d = idx >> 2, seg = idx & 3;
            wrv[t] = *(const float4*)&W[(size_t)d * CC + k0 + seg * 4];
        }
    };
    auto ldgWq = [&](int k0) {
        #pragma unroll
        for (int t = 0; t < 3; t++) {
            int idx = tid + t * 256;
            int d = idx >> 2, seg = idx & 3;
            int grow = (d >> 5) * 96 + (d & 31);
            wrv[t] = *(const float4*)&qkv_w[(size_t)grow * CC + k0 + seg * 4];
        }
    };
    auto stsW = [&](int buf) {
        #pragma unroll
        for (int t = 0; t < 3; t++) {
            int idx = tid + t * 256;
            int d = idx >> 2, seg = idx & 3;
            unsigned* dst = Wu + buf * 3840 + d * 20 + seg * 2;
            dst[0] = pk2h(wrv[t].x, wrv[t].y);
            dst[1] = pk2h(wrv[t].z, wrv[t].w);
        }
    };
    auto mmachunk = [&](const unsigned* Asrc, int c, int buf) {
        const unsigned* Wb = Wu + buf * 3840;
        int kw = c * 8;
        unsigned a[2][4];
        #pragma unroll
        for (int i = 0; i < 2; i++) {
            const unsigned* ap = Asrc + (m0w + 16 * i + gid) * AW + kw + tig;
            a[i][0] = ap[0];
            a[i][1] = ap[8 * AW];
            a[i][2] = ap[4];
            a[i][3] = ap[8 * AW + 4];
        }
        #pragma unroll
        for (int j = 0; j < 12; j++) {
            const unsigned* bp = Wb + (n0w + 8 * j + gid) * 20 + tig;
            unsigned b0 = bp[0], b1 = bp[4];
            mma16(acc[0][j], a[0][0], a[0][1], a[0][2], a[0][3], b0, b1);
            mma16(acc[1][j], a[1][0], a[1][1], a[1][2], a[1][3], b0, b1);
        }
    };

    // ---------------- q projection: Bu = fp16(A @ Wq^T + bq) ----------------
    zeroacc();
    ldgWq(0);
    #pragma unroll 1
    for (int c = 0; c < 12; c++) {
        stsW(c & 1);
        if (c < 11) ldgWq((c + 1) * 16);
        __syncthreads();
        mmachunk(Au, c, c & 1);
    }
    #pragma unroll
    for (int j = 0; j < 12; j++) {
        int c0 = n0w + 8 * j + 2 * tig;
        float b0 = __ldg(&qkv_b[(c0 >> 5) * 96 + (c0 & 31)]);
        float b1 = __ldg(&qkv_b[(c0 >> 5) * 96 + (c0 & 31) + 1]);
        #pragma unroll
        for (int i = 0; i < 2; i++) {
            int r = m0w + 16 * i + gid;
            Bu[r * AW + (c0 >> 1)]       = pk2h(acc[i][j][0] + b0, acc[i][j][1] + b1);
            Bu[(r + 8) * AW + (c0 >> 1)] = pk2h(acc[i][j][2] + b0, acc[i][j][3] + b1);
        }
    }
    __syncthreads();   // all warps done with Wu before kvT staging

    // ---------------- stage kvT (fp16): row (h*32+e), halves d 0..31 ----------------
    for (int idx = tid; idx < 192 * 16; idx += 256) {
        int row = idx >> 4, wd = idx & 15;
        int h = row >> 5, e = row & 31, d0 = wd * 2;
        const float* kvb = &g_kv[((size_t)bi * HEADS + h) * HEADC * HEADC];
        Wu[row * 20 + wd] = pk2h(kvb[d0 * 32 + e], kvb[(d0 + 1) * 32 + e]);
    }
    __syncthreads();

    // ---------------- attn: acc = x_h + q @ kv (per head) ----------------
    {
        // init acc from Au (fp16(x)); exact x re-added at the final store
        #pragma unroll
        for (int j = 0; j < 12; j++) {
            int c0 = n0w + 8 * j + 2 * tig;
            #pragma unroll
            for (int i = 0; i < 2; i++) {
                int r = m0w + 16 * i + gid;
                float2 lo = up2f(Au[r * AW + (c0 >> 1)]);
                float2 hi = up2f(Au[(r + 8) * AW + (c0 >> 1)]);
                acc[i][j][0] = lo.x; acc[i][j][1] = lo.y;
                acc[i][j][2] = hi.x; acc[i][j][3] = hi.y;
            }
        }
        #pragma unroll
        for (int s = 0; s < 2; s++) {
            unsigned qa[3][2][4];
            #pragma unroll
            for (int hh = 0; hh < 3; hh++) {
                #pragma unroll
                for (int i = 0; i < 2; i++) {
                    const unsigned* ap = Bu + (m0w + 16 * i + gid) * AW
                                       + (h0 + hh) * 16 + 8 * s + tig;
                    qa[hh][i][0] = ap[0];
                    qa[hh][i][1] = ap[8 * AW];
                    qa[hh][i][2] = ap[4];
                    qa[hh][i][3] = ap[8 * AW + 4];
                }
            }
            #pragma unroll
            for (int j = 0; j < 12; j++) {
                int hh = j >> 2;
                const unsigned* bp = Wu + ((h0 + hh) * 32 + 8 * (j & 3) + gid) * 20
                                   + 8 * s + tig;
                unsigned b0 = bp[0], b1 = bp[4];
                mma16(acc[0][j], qa[hh][0][0], qa[hh][0][1], qa[hh][0][2], qa[hh][0][3], b0, b1);
                mma16(acc[1][j], qa[hh][1][0], qa[hh][1][1], qa[hh][1][2], qa[hh][1][3], b0, b1);
            }
        }
        // ret -> Au (fp16)
        #pragma unroll
        for (int j = 0; j < 12; j++) {
            int c0 = n0w + 8 * j + 2 * tig;
            #pragma unroll
            for (int i = 0; i < 2; i++) {
                int r = m0w + 16 * i + gid;
                Au[r * AW + (c0 >> 1)]       = pk2h(acc[i][j][0], acc[i][j][1]);
                Au[(r + 8) * AW + (c0 >> 1)] = pk2h(acc[i][j][2], acc[i][j][3]);
            }
        }
    }
    __syncthreads();

    // ---------------- GEMM1: Bu = fp16(gelu(ret @ o1w^T + o1b)) ----------------
    zeroacc();
    ldgW(o1w, 0);
    #pragma unroll 1
    for (int c = 0; c < 12; c++) {
        stsW(c & 1);
        if (c < 11) ldgW(o1w, (c + 1) * 16);
        __syncthreads();
        mmachunk(Au, c, c & 1);
    }
    #pragma unroll
    for (int j = 0; j < 12; j++) {
        int c0 = n0w + 8 * j + 2 * tig;
        float b0 = __ldg(&o1b[c0]);
        float b1 = __ldg(&o1b[c0 + 1]);
        #pragma unroll
        for (int i = 0; i < 2; i++) {
            int r = m0w + 16 * i + gid;
            float t0 = acc[i][j][0] + b0;
            float t1 = acc[i][j][1] + b1;
            float t2 = acc[i][j][2] + b0;
            float t3 = acc[i][j][3] + b1;
            float g0 = 0.5f * t0 * (1.f + erff(t0 * 0.70710678118654752f));
            float g1 = 0.5f * t1 * (1.f + erff(t1 * 0.70710678118654752f));
            float g2 = 0.5f * t2 * (1.f + erff(t2 * 0.70710678118654752f));
            float g3 = 0.5f * t3 * (1.f + erff(t3 * 0.70710678118654752f));
            Bu[r * AW + (c0 >> 1)]       = pk2h(g0, g1);
            Bu[(r + 8) * AW + (c0 >> 1)] = pk2h(g2, g3);
        }
    }
    __syncthreads();

    // ---------------- GEMM2: out = h @ o2w^T + o2b + x ----------------
    zeroacc();
    ldgW(o2w, 0);
    #pragma unroll 1
    for (int c = 0; c < 12; c++) {
        stsW(c & 1);
        if (c < 11) ldgW(o2w, (c + 1) * 16);
        __syncthreads();
        mmachunk(Bu, c, c & 1);
    }
    __syncthreads();   // all mma reads of Bu done before F overlays it

    // raw fp32 acc -> F (stride 200), float2 stores (conflict-free per phase)
    #pragma unroll
    for (int j = 0; j < 12; j++) {
        int c0 = n0w + 8 * j + 2 * tig;
        #pragma unroll
        for (int i = 0; i < 2; i++) {
            int r = m0w + 16 * i + gid;
            *(float2*)&F[r * 200 + c0]       = make_float2(acc[i][j][0], acc[i][j][1]);
            *(float2*)&F[(r + 8) * 200 + c0] = make_float2(acc[i][j][2], acc[i][j][3]);
        }
    }
    __syncthreads();

    // coalesced epilogue store: + o2b + exact x
    for (int idx = tid; idx < TM * 48; idx += 256) {
        int p = idx / 48, c4 = (idx % 48) * 4;
        float4 av = *(float4*)&F[p * 200 + c4];
        float4 bv = *(const float4*)&o2b[c4];
        float4 xv = *(const float4*)&x[(size_t)(m0 + p) * CC + c4];
        av.x += bv.x + xv.x;
        av.y += bv.y + xv.y;
        av.z += bv.z + xv.z;
        av.w += bv.w + xv.w;
        *(float4*)&out[(size_t)(m0 + p) * CC + c4] = av;
    }
}

// ---------------------------------------------------------------------------

extern "C" void kernel_launch(void* const* d_in, const int* in_sizes, int n_in,
                              void* d_out, int out_size)
{
    const float* x     = (const float*)d_in[0];
    const float* qkv_w = (const float*)d_in[1];
    const float* qkv_b = (const float*)d_in[2];
    const float* o1w   = (const float*)d_in[3];
    const float* o1b   = (const float*)d_in[4];
    const float* o2w   = (const float*)d_in[5];
    const float* o2b   = (const float*)d_in[6];
    const float* klw   = (const float*)d_in[7];
    const float* klb   = (const float*)d_in[8];
    const float* vlw   = (const float*)d_in[9];
    const float* vlb   = (const float*)d_in[10];
    float* out = (float*)d_out;

    const int smem1 = (5120 + 2560 + 128 * 68) * 4;   // 65,536 B
    cudaFuncSetAttribute(k1_kv, cudaFuncAttributeMaxDynamicSharedMemorySize, smem1);
    cudaFuncSetAttribute(k2_attn_mlp, cudaFuncAttributeMaxDynamicSharedMemorySize, K2_SMEM);

    zero_kv_kernel<<<(BB * HEADS * HEADC * HEADC + 255) / 256, 256>>>();

    dim3 g1(HEADS, MTOT / TM);
    k1_kv<<<g1, 256, smem1>>>(x, qkv_w, qkv_b, klw, klb, vlw, vlb);

    k2_attn_mlp<<<MTOT / TM, 256, K2_SMEM>>>(x, qkv_w, qkv_b, o1w, o1b, o2w, o2b, out);
}

// round 16
// speedup vs baseline: 1.4324x; 1.1280x over previous
#include <cuda_runtime.h>
#include <cuda_fp16.h>
#include <math.h>
#include <cstdint>

#define BB 4
#define NN 65536
#define CC 192
#define HEADS 6
#define HEADC 32
#define MTOT (BB*NN)
#define TM 128
#define EPS 1e-5f

// device-global scratch
__device__ float g_kv[BB * HEADS * HEADC * HEADC];     // kv = (k^T v)/N per (b,h)
__device__ float g_M[BB * CC * CC];                    // M[bi][j][c] = sum_d Wq[h*96+d][c]*kv[d][e], j=h*32+e
__device__ float g_cvec[BB * CC];                      // cvec[bi][j] = sum_d bq[h*96+d]*kv[d][e]

__global__ void zero_kv_kernel() {
    int i = blockIdx.x * blockDim.x + threadIdx.x;
    if (i < BB * HEADS * HEADC * HEADC) g_kv[i] = 0.f;
}

__device__ __forceinline__ unsigned pk2h(float a, float b) {
    __half2 h = __floats2half2_rn(a, b);
    return *reinterpret_cast<unsigned*>(&h);
}
__device__ __forceinline__ float2 up2f(unsigned w) {
    __half2 h = *reinterpret_cast<__half2*>(&w);
    return __half22float2(h);
}

__device__ __forceinline__ void mma16(float* c,
    unsigned a0, unsigned a1, unsigned a2, unsigned a3,
    unsigned b0, unsigned b1)
{
    asm volatile(
        "mma.sync.aligned.m16n8k16.row.col.f32.f16.f16.f32 "
        "{%0,%1,%2,%3}, {%4,%5,%6,%7}, {%8,%9}, {%0,%1,%2,%3};"
        : "+f"(c[0]), "+f"(c[1]), "+f"(c[2]), "+f"(c[3])
        : "r"(a0), "r"(a1), "r"(a2), "r"(a3), "r"(b0), "r"(b1));
}

// ---------------------------------------------------------------------------
// Kernel 1: k,v projection (one head per block) via fp16 mma, LN(k), LN(v),
// kv outer product via tensor core (32x32x128 mma on transposed LN'd k/v).
// grid: (HEADS, MTOT/TM), block: 256
// smem: staging Au/Wu (7680 w, reused as T[64][68]w) + Res[128][68]f = 65,536 B
// ---------------------------------------------------------------------------
__global__ __launch_bounds__(256) void k1_kv(
    const float* __restrict__ x, const float* __restrict__ qkv_w,
    const float* __restrict__ qkv_b,
    const float* __restrict__ klw, const float* __restrict__ klb,
    const float* __restrict__ vlw, const float* __restrict__ vlb)
{
    extern __shared__ float sm[];
    unsigned* Au = (unsigned*)sm;                // 2*128*20 = 5120 w
    unsigned* Wu = (unsigned*)sm + 5120;         // 2*64*20  = 2560 w
    float*    Res = sm + 5120 + 2560;            // 128*68 floats
    unsigned* T  = Au;                           // kT/vT [64 rows][68 w], overlays staging

    const int tid  = threadIdx.x;
    const int head = blockIdx.x;
    const int m0   = blockIdx.y * TM;
    const int wbase = head * 96 + 32;            // k rows, then v rows

    const int warp = tid >> 5, lane = tid & 31;
    const int gid = lane >> 2, tig = lane & 3;
    const int m0w = (warp >> 1) * 32, n0w = (warp & 1) * 32;

    const int sp   = tid >> 1;                   // staging row
    const int sseg = tid & 1;                    // 8-half segment

    float4 xr[2], wr[2];

    float acc[2][4][4];
    #pragma unroll
    for (int i = 0; i < 2; i++)
        #pragma unroll
        for (int j = 0; j < 4; j++)
            #pragma unroll
            for (int e = 0; e < 4; e++) acc[i][j][e] = 0.f;

    // prefetch chunk 0 (k = 0..15)
    {
        const float* xp = &x[(size_t)(m0 + sp) * CC + sseg * 8];
        xr[0] = *(const float4*)xp;
        xr[1] = *(const float4*)(xp + 4);
        if (tid < 128) {
            const float* wp = &qkv_w[(size_t)(wbase + sp) * CC + sseg * 8];
            wr[0] = *(const float4*)wp;
            wr[1] = *(const float4*)(wp + 4);
        }
    }

    #pragma unroll 1
    for (int c = 0; c < 12; c++) {
        // STS chunk c (fp16-pack once here)
        {
            unsigned* da = Au + (c & 1) * 2560 + sp * 20 + sseg * 4;
            da[0] = pk2h(xr[0].x, xr[0].y);
            da[1] = pk2h(xr[0].z, xr[0].w);
            da[2] = pk2h(xr[1].x, xr[1].y);
            da[3] = pk2h(xr[1].z, xr[1].w);
            if (tid < 128) {
                unsigned* dw = Wu + (c & 1) * 1280 + sp * 20 + sseg * 4;
                dw[0] = pk2h(wr[0].x, wr[0].y);
                dw[1] = pk2h(wr[0].z, wr[0].w);
                dw[2] = pk2h(wr[1].x, wr[1].y);
                dw[3] = pk2h(wr[1].z, wr[1].w);
            }
        }
        // LDG chunk c+1
        if (c < 11) {
            int k0 = (c + 1) * 16;
            const float* xp = &x[(size_t)(m0 + sp) * CC + k0 + sseg * 8];
            xr[0] = *(const float4*)xp;
            xr[1] = *(const float4*)(xp + 4);
            if (tid < 128) {
                const float* wp = &qkv_w[(size_t)(wbase + sp) * CC + k0 + sseg * 8];
                wr[0] = *(const float4*)wp;
                wr[1] = *(const float4*)(wp + 4);
            }
        }
        __syncthreads();
        const unsigned* Ab = Au + (c & 1) * 2560;
        const unsigned* Wb = Wu + (c & 1) * 1280;
        unsigned a[2][4];
        #pragma unroll
        for (int i = 0; i < 2; i++) {
            const unsigned* ap = Ab + (m0w + 16 * i + gid) * 20 + tig;
            a[i][0] = ap[0];
            a[i][1] = ap[8 * 20];
            a[i][2] = ap[4];
            a[i][3] = ap[8 * 20 + 4];
        }
        #pragma unroll
        for (int j = 0; j < 4; j++) {
            const unsigned* bp = Wb + (n0w + 8 * j + gid) * 20 + tig;
            unsigned b0 = bp[0], b1 = bp[4];
            mma16(acc[0][j], a[0][0], a[0][1], a[0][2], a[0][3], b0, b1);
            mma16(acc[1][j], a[1][0], a[1][1], a[1][2], a[1][3], b0, b1);
        }
    }

    // epilogue: +bias -> Res (fp32)
    #pragma unroll
    for (int j = 0; j < 4; j++) {
        int c0 = n0w + 8 * j + 2 * tig;
        float b0 = __ldg(&qkv_b[wbase + c0]);
        float b1 = __ldg(&qkv_b[wbase + c0 + 1]);
        #pragma unroll
        for (int i = 0; i < 2; i++) {
            int r = m0w + 16 * i + gid;
            Res[r * 68 + c0]           = acc[i][j][0] + b0;
            Res[r * 68 + c0 + 1]       = acc[i][j][1] + b1;
            Res[(r + 8) * 68 + c0]     = acc[i][j][2] + b0;
            Res[(r + 8) * 68 + c0 + 1] = acc[i][j][3] + b1;
        }
    }
    __syncthreads();

    // LN on k (cols 0..31) and v (cols 32..63); ddof=1, denom = std + eps
    {
        int p = tid & 127;
        int which = tid >> 7;
        int base = which ? 32 : 0;
        const float* lw = which ? vlw : klw;
        const float* lb = which ? vlb : klb;
        float s = 0.f, s2 = 0.f;
        #pragma unroll
        for (int c = 0; c < 32; c++) {
            float v = Res[p * 68 + base + c];
            s += v; s2 += v * v;
        }
        float mean = s * (1.f / 32.f);
        float var = (s2 - s * mean) * (1.f / 31.f);
        var = fmaxf(var, 0.f);
        float inv = 1.f / (sqrtf(var) + EPS);
        #pragma unroll
        for (int c = 0; c < 32; c++) {
            float v = Res[p * 68 + base + c];
            Res[p * 68 + base + c] =
                __ldg(&lw[head * 32 + c]) * ((v - mean) * inv) + __ldg(&lb[head * 32 + c]);
        }
    }
    __syncthreads();

    // transpose LN'd k/v to fp16: T[row][pw]  (row<32: k dim d; row>=32: v dim e)
    for (int idx = tid; idx < 64 * 64; idx += 256) {
        int row = idx >> 6, pw = idx & 63;
        T[row * 68 + pw] = pk2h(Res[(2 * pw) * 68 + row], Res[(2 * pw + 1) * 68 + row]);
    }
    __syncthreads();

    // kv outer product via mma: kv[d][e] = sum_p k[p][d] v[p][e]; warps 0-3
    if (warp < 4) {
        const int mw = (warp >> 1) * 16, nw = (warp & 1) * 16;
        float kacc[2][4];
        #pragma unroll
        for (int j = 0; j < 2; j++)
            #pragma unroll
            for (int e = 0; e < 4; e++) kacc[j][e] = 0.f;
        #pragma unroll
        for (int s = 0; s < 8; s++) {
            const unsigned* ap = T + (mw + gid) * 68 + s * 8 + tig;
            unsigned a0 = ap[0], a1 = ap[8 * 68], a2 = ap[4], a3 = ap[8 * 68 + 4];
            #pragma unroll
            for (int j = 0; j < 2; j++) {
                const unsigned* bp = T + (32 + nw + 8 * j + gid) * 68 + s * 8 + tig;
                mma16(kacc[j], a0, a1, a2, a3, bp[0], bp[4]);
            }
        }
        int bi = m0 / NN;
        float* kvb = &g_kv[((size_t)bi * HEADS + head) * HEADC * HEADC];
        const float sc = 1.f / (float)NN;
        #pragma unroll
        for (int j = 0; j < 2; j++) {
            int e0 = nw + 8 * j + 2 * tig;
            atomicAdd(&kvb[(mw + gid) * 32 + e0],     kacc[j][0] * sc);
            atomicAdd(&kvb[(mw + gid) * 32 + e0 + 1], kacc[j][1] * sc);
            atomicAdd(&kvb[(mw + gid + 8) * 32 + e0],     kacc[j][2] * sc);
            atomicAdd(&kvb[(mw + gid + 8) * 32 + e0 + 1], kacc[j][3] * sc);
        }
    }
}

// ---------------------------------------------------------------------------
// Kernel mid: M[bi][h*32+e][c] = sum_d Wq[h*96+d][c] * kv[d][e]  (fp32)
//             cvec[bi][h*32+e] = sum_d bq[h*96+d] * kv[d][e]
// grid: BB*HEADS blocks, 256 threads
// ---------------------------------------------------------------------------
__global__ __launch_bounds__(256) void k_mid(
    const float* __restrict__ qkv_w, const float* __restrict__ qkv_b)
{
    __shared__ float kvs[32 * 32];
    __shared__ float Ws[32 * CC];

    const int tid = threadIdx.x;
    const int bi = blockIdx.x / HEADS, h = blockIdx.x % HEADS;

    for (int i = tid; i < 1024; i += 256)
        kvs[i] = g_kv[((size_t)bi * HEADS + h) * 1024 + i];
    for (int i = tid; i < 32 * CC; i += 256) {
        int d = i / CC, c = i % CC;
        Ws[i] = qkv_w[(size_t)(h * 96 + d) * CC + c];
    }
    __syncthreads();

    for (int o = tid; o < 32 * CC; o += 256) {
        int e = o / CC, c = o % CC;
        float s = 0.f;
        #pragma unroll
        for (int d = 0; d < 32; d++)
            s += kvs[d * 32 + e] * Ws[d * CC + c];
        g_M[((size_t)bi * CC + h * 32 + e) * CC + c] = s;
    }
    if (tid < 32) {
        float s = 0.f;
        #pragma unroll
        for (int d = 0; d < 32; d++)
            s += __ldg(&qkv_b[h * 96 + d]) * kvs[d * 32 + tid];
        g_cvec[bi * CC + h * 32 + tid] = s;
    }
}

// ---------------------------------------------------------------------------
// Kernel 2: three identical 192x192 GEMMs, fp16 mma:
//   GEMM0: ret = x @ M^T + cvec + x     (M rows are output cols)
//   GEMM1: h   = gelu(ret @ o1w^T + o1b)
//   GEMM2: out = h @ o2w^T + o2b + x (exact x)
// 256 threads, warp grid 2(M) x 2(N, 96 cols each).
// smem: Au[128][100w] + Bu[128][100w] + Wu[2][192][20w] = 133,120 B
// ---------------------------------------------------------------------------
#define AW 100
#define K2_SMEM ((12800 + 12800 + 2 * 3840) * 4)

__global__ __launch_bounds__(256) void k2_mlp(
    const float* __restrict__ x,
    const float* __restrict__ o1w, const float* __restrict__ o1b,
    const float* __restrict__ o2w, const float* __restrict__ o2b,
    float* __restrict__ out)
{
    extern __shared__ float sm[];
    unsigned* Au = (unsigned*)sm;            // 128*100 w
    unsigned* Bu = Au + 12800;               // 128*100 w
    unsigned* Wu = Bu + 12800;               // 2 * 192*20 w
    float*    F  = sm;                       // fp32 final stage, stride 200

    const int tid = threadIdx.x;
    const int m0  = blockIdx.x * TM;
    const int bi  = m0 / NN;
    const int warp = tid >> 5, lane = tid & 31;
    const int gid = lane >> 2, tig = lane & 3;
    const int m0w = (warp >> 1) * 32, n0w = (warp & 1) * 96;

    const float* Mb = g_M + (size_t)bi * CC * CC;
    const float* cvb = g_cvec + bi * CC;

    // stage 0: x -> Au (fp16), 24 segments x 8 floats = 192 channels
    for (int idx = tid; idx < TM * 24; idx += 256) {
        int p = idx / 24, seg = idx % 24;
        const float* xp = &x[(size_t)(m0 + p) * CC + seg * 8];
        float4 v0 = *(const float4*)xp;
        float4 v1 = *(const float4*)(xp + 4);
        unsigned* dst = Au + p * AW + seg * 4;
        dst[0] = pk2h(v0.x, v0.y); dst[1] = pk2h(v0.z, v0.w);
        dst[2] = pk2h(v1.x, v1.y); dst[3] = pk2h(v1.z, v1.w);
    }
    __syncthreads();

    float4 wrv[3];
    float acc[2][12][4];

    auto zeroacc = [&]() {
        #pragma unroll
        for (int i = 0; i < 2; i++)
            #pragma unroll
            for (int j = 0; j < 12; j++)
                #pragma unroll
                for (int e = 0; e < 4; e++) acc[i][j][e] = 0.f;
    };
    auto ldgW = [&](const float* W, int k0) {
        #pragma unroll
        for (int t = 0; t < 3; t++) {
            int idx = tid + t * 256;
            int d = idx >> 2, seg = idx & 3;
            wrv[t] = *(const float4*)&W[(size_t)d * CC + k0 + seg * 4];
        }
    };
    auto stsW = [&](int buf) {
        #pragma unroll
        for (int t = 0; t < 3; t++) {
            int idx = tid + t * 256;
            int d = idx >> 2, seg = idx & 3;
            unsigned* dst = Wu + buf * 3840 + d * 20 + seg * 2;
            dst[0] = pk2h(wrv[t].x, wrv[t].y);
            dst[1] = pk2h(wrv[t].z, wrv[t].w);
        }
    };
    auto mmachunk = [&](const unsigned* Asrc, int c, int buf) {
        const unsigned* Wb = Wu + buf * 3840;
        int kw = c * 8;
        unsigned a[2][4];
        #pragma unroll
        for (int i = 0; i < 2; i++) {
            const unsigned* ap = Asrc + (m0w + 16 * i + gid) * AW + kw + tig;
            a[i][0] = ap[0];
            a[i][1] = ap[8 * AW];
            a[i][2] = ap[4];
            a[i][3] = ap[8 * AW + 4];
        }
        #pragma unroll
        for (int j = 0; j < 12; j++) {
            const unsigned* bp = Wb + (n0w + 8 * j + gid) * 20 + tig;
            unsigned b0 = bp[0], b1 = bp[4];
            mma16(acc[0][j], a[0][0], a[0][1], a[0][2], a[0][3], b0, b1);
            mma16(acc[1][j], a[1][0], a[1][1], a[1][2], a[1][3], b0, b1);
        }
    };
    auto gemm = [&](const unsigned* Asrc, const float* W) {
        zeroacc();
        ldgW(W, 0);
        #pragma unroll 1
        for (int c = 0; c < 12; c++) {
            stsW(c & 1);
            if (c < 11) ldgW(W, (c + 1) * 16);
            __syncthreads();
            mmachunk(Asrc, c, c & 1);
        }
    };

    // ---------------- GEMM0: ret = x @ M^T + cvec + fp16(x) -> Bu ----------------
    gemm(Au, Mb);
    #pragma unroll
    for (int j = 0; j < 12; j++) {
        int c0 = n0w + 8 * j + 2 * tig;
        float cv0 = __ldg(&cvb[c0]);
        float cv1 = __ldg(&cvb[c0 + 1]);
        #pragma unroll
        for (int i = 0; i < 2; i++) {
            int r = m0w + 16 * i + gid;
            float2 x0 = up2f(Au[r * AW + (c0 >> 1)]);
            float2 x1 = up2f(Au[(r + 8) * AW + (c0 >> 1)]);
            Bu[r * AW + (c0 >> 1)]       = pk2h(acc[i][j][0] + cv0 + x0.x, acc[i][j][1] + cv1 + x0.y);
            Bu[(r + 8) * AW + (c0 >> 1)] = pk2h(acc[i][j][2] + cv0 + x1.x, acc[i][j][3] + cv1 + x1.y);
        }
    }

    // ---------------- GEMM1: h = gelu(ret @ o1w^T + o1b) -> Au ----------------
    gemm(Bu, o1w);
    #pragma unroll
    for (int j = 0; j < 12; j++) {
        int c0 = n0w + 8 * j + 2 * tig;
        float b0 = __ldg(&o1b[c0]);
        float b1 = __ldg(&o1b[c0 + 1]);
        #pragma unroll
        for (int i = 0; i < 2; i++) {
            int r = m0w + 16 * i + gid;
            float t0 = acc[i][j][0] + b0;
            float t1 = acc[i][j][1] + b1;
            float t2 = acc[i][j][2] + b0;
            float t3 = acc[i][j][3] + b1;
            float g0 = 0.5f * t0 * (1.f + erff(t0 * 0.70710678118654752f));
            float g1 = 0.5f * t1 * (1.f + erff(t1 * 0.70710678118654752f));
            float g2 = 0.5f * t2 * (1.f + erff(t2 * 0.70710678118654752f));
            float g3 = 0.5f * t3 * (1.f + erff(t3 * 0.70710678118654752f));
            Au[r * AW + (c0 >> 1)]       = pk2h(g0, g1);
            Au[(r + 8) * AW + (c0 >> 1)] = pk2h(g2, g3);
        }
    }

    // ---------------- GEMM2: out = h @ o2w^T + o2b + exact x ----------------
    gemm(Au, o2w);
    __syncthreads();   // all mma reads of Au/Bu done before F overlays them

    #pragma unroll
    for (int j = 0; j < 12; j++) {
        int c0 = n0w + 8 * j + 2 * tig;
        #pragma unroll
        for (int i = 0; i < 2; i++) {
            int r = m0w + 16 * i + gid;
            *(float2*)&F[r * 200 + c0]       = make_float2(acc[i][j][0], acc[i][j][1]);
            *(float2*)&F[(r + 8) * 200 + c0] = make_float2(acc[i][j][2], acc[i][j][3]);
        }
    }
    __syncthreads();

    for (int idx = tid; idx < TM * 48; idx += 256) {
        int p = idx / 48, c4 = (idx % 48) * 4;
        float4 av = *(float4*)&F[p * 200 + c4];
        float4 bv = *(const float4*)&o2b[c4];
        float4 xv = *(const float4*)&x[(size_t)(m0 + p) * CC + c4];
        av.x += bv.x + xv.x;
        av.y += bv.y + xv.y;
        av.z += bv.z + xv.z;
        av.w += bv.w + xv.w;
        *(float4*)&out[(size_t)(m0 + p) * CC + c4] = av;
    }
}

// ---------------------------------------------------------------------------

extern "C" void kernel_launch(void* const* d_in, const int* in_sizes, int n_in,
                              void* d_out, int out_size)
{
    const float* x     = (const float*)d_in[0];
    const float* qkv_w = (const float*)d_in[1];
    const float* qkv_b = (const float*)d_in[2];
    const float* o1w   = (const float*)d_in[3];
    const float* o1b   = (const float*)d_in[4];
    const float* o2w   = (const float*)d_in[5];
    const float* o2b   = (const float*)d_in[6];
    const float* klw   = (const float*)d_in[7];
    const float* klb   = (const float*)d_in[8];
    const float* vlw   = (const float*)d_in[9];
    const float* vlb   = (const float*)d_in[10];
    float* out = (float*)d_out;

    const int smem1 = (5120 + 2560 + 128 * 68) * 4;   // 65,536 B
    cudaFuncSetAttribute(k1_kv, cudaFuncAttributeMaxDynamicSharedMemorySize, smem1);
    cudaFuncSetAttribute(k2_mlp, cudaFuncAttributeMaxDynamicSharedMemorySize, K2_SMEM);

    zero_kv_kernel<<<(BB * HEADS * HEADC * HEADC + 255) / 256, 256>>>();

    dim3 g1(HEADS, MTOT / TM);
    k1_kv<<<g1, 256, smem1>>>(x, qkv_w, qkv_b, klw, klb, vlw, vlb);

    k_mid<<<BB * HEADS, 256>>>(qkv_w, qkv_b);

    k2_mlp<<<MTOT / TM, 256, K2_SMEM>>>(x, o1w, o1b, o2w, o2b, out);
}

// round 17
// speedup vs baseline: 1.4769x; 1.0311x over previous
#include <cuda_runtime.h>
#include <cuda_fp16.h>
#include <math.h>
#include <cstdint>

#define BB 4
#define NN 65536
#define CC 192
#define HEADS 6
#define HEADC 32
#define MTOT (BB*NN)
#define TM 128
#define EPS 1e-5f

// device-global scratch
__device__ float g_kv[BB * HEADS * HEADC * HEADC];     // kv = (k^T v)/N per (b,h)
__device__ float g_M[BB * CC * CC];                    // M[bi][h*32+e][c] = sum_d Wq[h*96+d][c]*kv[d][e]
__device__ float g_cvec[BB * CC];                      // cvec[bi][h*32+e] = sum_d bq[h*96+d]*kv[d][e]

__global__ void zero_kv_kernel() {
    int i = blockIdx.x * blockDim.x + threadIdx.x;
    if (i < BB * HEADS * HEADC * HEADC) g_kv[i] = 0.f;
}

__device__ __forceinline__ unsigned pk2h(float a, float b) {
    __half2 h = __floats2half2_rn(a, b);
    return *reinterpret_cast<unsigned*>(&h);
}
__device__ __forceinline__ float2 up2f(unsigned w) {
    __half2 h = *reinterpret_cast<__half2*>(&w);
    return __half22float2(h);
}

__device__ __forceinline__ void mma16(float* c,
    unsigned a0, unsigned a1, unsigned a2, unsigned a3,
    unsigned b0, unsigned b1)
{
    asm volatile(
        "mma.sync.aligned.m16n8k16.row.col.f32.f16.f16.f32 "
        "{%0,%1,%2,%3}, {%4,%5,%6,%7}, {%8,%9}, {%0,%1,%2,%3};"
        : "+f"(c[0]), "+f"(c[1]), "+f"(c[2]), "+f"(c[3])
        : "r"(a0), "r"(a1), "r"(a2), "r"(a3), "r"(b0), "r"(b1));
}

// ---------------------------------------------------------------------------
// Kernel 1: k,v projection for a HEAD PAIR per block (128 outputs) via fp16
// mma, LN(k), LN(v) for both heads, kv outer products via tensor core.
// grid: (HEADS/2, MTOT/TM), block: 256
// smem: Au[2][128][20w] + Wu[2][128][20w] + Res[128][132]f = 108,544 B
// Res stride 132; cols 0-63 head A (k then v), 64-127 head B.
// ---------------------------------------------------------------------------
#define RST 132
#define K1_SMEM ((5120 + 5120) * 4 + 128 * RST * 4)

__global__ __launch_bounds__(256) void k1_kv(
    const float* __restrict__ x, const float* __restrict__ qkv_w,
    const float* __restrict__ qkv_b,
    const float* __restrict__ klw, const float* __restrict__ klb,
    const float* __restrict__ vlw, const float* __restrict__ vlb)
{
    extern __shared__ float sm[];
    unsigned* Au = (unsigned*)sm;                // 2*128*20 = 5120 w
    unsigned* Wu = (unsigned*)sm + 5120;         // 2*128*20 = 5120 w
    float*    Res = sm + 10240;                  // 128*132 floats
    unsigned* T  = Au;                           // kT/vT [128 rows][68w], overlays staging

    const int tid = threadIdx.x;
    const int hp  = blockIdx.x;                  // head pair: heads 2hp, 2hp+1
    const int m0  = blockIdx.y * TM;

    const int warp = tid >> 5, lane = tid & 31;
    const int gid = lane >> 2, tig = lane & 3;
    const int m0w = (warp >> 1) * 32, n0w = (warp & 1) * 64;

    const int sp   = tid >> 1;                   // staging row (0..127)
    const int sseg = tid & 1;                    // 8-float segment

    const int wrow = (2 * hp + (sp >> 6)) * 96 + 32 + (sp & 63);  // qkv_w row for Wu row sp

    float4 xr[2], wr[2];

    float acc[2][8][4];
    #pragma unroll
    for (int i = 0; i < 2; i++)
        #pragma unroll
        for (int j = 0; j < 8; j++)
            #pragma unroll
            for (int e = 0; e < 4; e++) acc[i][j][e] = 0.f;

    // prefetch chunk 0 (k = 0..15)
    {
        const float* xp = &x[(size_t)(m0 + sp) * CC + sseg * 8];
        xr[0] = *(const float4*)xp;
        xr[1] = *(const float4*)(xp + 4);
        const float* wp = &qkv_w[(size_t)wrow * CC + sseg * 8];
        wr[0] = *(const float4*)wp;
        wr[1] = *(const float4*)(wp + 4);
    }

    #pragma unroll 1
    for (int c = 0; c < 12; c++) {
        // STS chunk c (fp16-pack once)
        {
            unsigned* da = Au + (c & 1) * 2560 + sp * 20 + sseg * 4;
            da[0] = pk2h(xr[0].x, xr[0].y);
            da[1] = pk2h(xr[0].z, xr[0].w);
            da[2] = pk2h(xr[1].x, xr[1].y);
            da[3] = pk2h(xr[1].z, xr[1].w);
            unsigned* dw = Wu + (c & 1) * 2560 + sp * 20 + sseg * 4;
            dw[0] = pk2h(wr[0].x, wr[0].y);
            dw[1] = pk2h(wr[0].z, wr[0].w);
            dw[2] = pk2h(wr[1].x, wr[1].y);
            dw[3] = pk2h(wr[1].z, wr[1].w);
        }
        // LDG chunk c+1
        if (c < 11) {
            int k0 = (c + 1) * 16;
            const float* xp = &x[(size_t)(m0 + sp) * CC + k0 + sseg * 8];
            xr[0] = *(const float4*)xp;
            xr[1] = *(const float4*)(xp + 4);
            const float* wp = &qkv_w[(size_t)wrow * CC + k0 + sseg * 8];
            wr[0] = *(const float4*)wp;
            wr[1] = *(const float4*)(wp + 4);
        }
        __syncthreads();
        const unsigned* Ab = Au + (c & 1) * 2560;
        const unsigned* Wb = Wu + (c & 1) * 2560;
        unsigned a[2][4];
        #pragma unroll
        for (int i = 0; i < 2; i++) {
            const unsigned* ap = Ab + (m0w + 16 * i + gid) * 20 + tig;
            a[i][0] = ap[0];
            a[i][1] = ap[8 * 20];
            a[i][2] = ap[4];
            a[i][3] = ap[8 * 20 + 4];
        }
        #pragma unroll
        for (int j = 0; j < 8; j++) {
            const unsigned* bp = Wb + (n0w + 8 * j + gid) * 20 + tig;
            unsigned b0 = bp[0], b1 = bp[4];
            mma16(acc[0][j], a[0][0], a[0][1], a[0][2], a[0][3], b0, b1);
            mma16(acc[1][j], a[1][0], a[1][1], a[1][2], a[1][3], b0, b1);
        }
    }

    // epilogue: +bias -> Res (fp32)
    #pragma unroll
    for (int j = 0; j < 8; j++) {
        int c0 = n0w + 8 * j + 2 * tig;
        int br0 = (2 * hp + (c0 >> 6)) * 96 + 32 + (c0 & 63);
        float b0 = __ldg(&qkv_b[br0]);
        float b1 = __ldg(&qkv_b[br0 + 1]);
        #pragma unroll
        for (int i = 0; i < 2; i++) {
            int r = m0w + 16 * i + gid;
            Res[r * RST + c0]           = acc[i][j][0] + b0;
            Res[r * RST + c0 + 1]       = acc[i][j][1] + b1;
            Res[(r + 8) * RST + c0]     = acc[i][j][2] + b0;
            Res[(r + 8) * RST + c0 + 1] = acc[i][j][3] + b1;
        }
    }
    __syncthreads();

    // LN: 512 (row, group) jobs; group g: cols 32g..32g+31
    //   g=0: k head 2hp, g=1: v head 2hp, g=2: k head 2hp+1, g=3: v head 2hp+1
    #pragma unroll
    for (int job = tid; job < 512; job += 256) {
        int p = job & 127, g = job >> 7;
        int base = g * 32;
        int gh = 2 * hp + (g >> 1);
        const float* lw = (g & 1) ? vlw : klw;
        const float* lb = (g & 1) ? vlb : klb;
        float s = 0.f, s2 = 0.f;
        #pragma unroll
        for (int cc2 = 0; cc2 < 32; cc2++) {
            float v = Res[p * RST + base + cc2];
            s += v; s2 += v * v;
        }
        float mean = s * (1.f / 32.f);
        float var = (s2 - s * mean) * (1.f / 31.f);
        var = fmaxf(var, 0.f);
        float inv = 1.f / (sqrtf(var) + EPS);
        #pragma unroll
        for (int cc2 = 0; cc2 < 32; cc2++) {
            float v = Res[p * RST + base + cc2];
            Res[p * RST + base + cc2] =
                __ldg(&lw[gh * 32 + cc2]) * ((v - mean) * inv) + __ldg(&lb[gh * 32 + cc2]);
        }
    }
    __syncthreads();

    // transpose LN'd k/v to fp16: T[row][pw], row = Res col, pw = pixel pair
    for (int idx = tid; idx < 128 * 64; idx += 256) {
        int row = idx >> 6, pw = idx & 63;
        T[row * 68 + pw] = pk2h(Res[(2 * pw) * RST + row], Res[(2 * pw + 1) * RST + row]);
    }
    __syncthreads();

    // kv outer products via mma: head h = warp>>2 (local), subtile = warp&3
    {
        int h = warp >> 2, sub = warp & 3;
        const int mw = (sub >> 1) * 16, nw = (sub & 1) * 16;
        const unsigned* Tk = T + (h * 64) * 68;        // k rows for this head
        const unsigned* Tv = T + (h * 64 + 32) * 68;   // v rows
        float kacc[2][4];
        #pragma unroll
        for (int j = 0; j < 2; j++)
            #pragma unroll
            for (int e = 0; e < 4; e++) kacc[j][e] = 0.f;
        #pragma unroll
        for (int s = 0; s < 8; s++) {
            const unsigned* ap = Tk + (mw + gid) * 68 + s * 8 + tig;
            unsigned a0 = ap[0], a1 = ap[8 * 68], a2 = ap[4], a3 = ap[8 * 68 + 4];
            #pragma unroll
            for (int j = 0; j < 2; j++) {
                const unsigned* bp = Tv + (nw + 8 * j + gid) * 68 + s * 8 + tig;
                mma16(kacc[j], a0, a1, a2, a3, bp[0], bp[4]);
            }
        }
        int bi = m0 / NN;
        float* kvb = &g_kv[((size_t)bi * HEADS + 2 * hp + h) * HEADC * HEADC];
        const float sc = 1.f / (float)NN;
        #pragma unroll
        for (int j = 0; j < 2; j++) {
            int e0 = nw + 8 * j + 2 * tig;
            atomicAdd(&kvb[(mw + gid) * 32 + e0],     kacc[j][0] * sc);
            atomicAdd(&kvb[(mw + gid) * 32 + e0 + 1], kacc[j][1] * sc);
            atomicAdd(&kvb[(mw + gid + 8) * 32 + e0],     kacc[j][2] * sc);
            atomicAdd(&kvb[(mw + gid + 8) * 32 + e0 + 1], kacc[j][3] * sc);
        }
    }
}

// ---------------------------------------------------------------------------
// Kernel mid: M[bi][h*32+e][c] = sum_d Wq[h*96+d][c] * kv[d][e]  (fp32)
//             cvec[bi][h*32+e] = sum_d bq[h*96+d] * kv[d][e]
// grid: BB*HEADS blocks, 256 threads
// ---------------------------------------------------------------------------
__global__ __launch_bounds__(256) void k_mid(
    const float* __restrict__ qkv_w, const float* __restrict__ qkv_b)
{
    __shared__ float kvs[32 * 32];
    __shared__ float Ws[32 * CC];

    const int tid = threadIdx.x;
    const int bi = blockIdx.x / HEADS, h = blockIdx.x % HEADS;

    for (int i = tid; i < 1024; i += 256)
        kvs[i] = g_kv[((size_t)bi * HEADS + h) * 1024 + i];
    for (int i = tid; i < 32 * CC; i += 256) {
        int d = i / CC, c = i % CC;
        Ws[i] = qkv_w[(size_t)(h * 96 + d) * CC + c];
    }
    __syncthreads();

    for (int o = tid; o < 32 * CC; o += 256) {
        int e = o / CC, c = o % CC;
        float s = 0.f;
        #pragma unroll
        for (int d = 0; d < 32; d++)
            s += kvs[d * 32 + e] * Ws[d * CC + c];
        g_M[((size_t)bi * CC + h * 32 + e) * CC + c] = s;
    }
    if (tid < 32) {
        float s = 0.f;
        #pragma unroll
        for (int d = 0; d < 32; d++)
            s += __ldg(&qkv_b[h * 96 + d]) * kvs[d * 32 + tid];
        g_cvec[bi * CC + h * 32 + tid] = s;
    }
}

// ---------------------------------------------------------------------------
// Kernel 2: three identical 192x192 GEMMs, fp16 mma (unchanged from R16):
//   GEMM0: ret = x @ M^T + cvec + x ; GEMM1: gelu MLP ; GEMM2: out (+exact x)
// ---------------------------------------------------------------------------
#define AW 100
#define K2_SMEM ((12800 + 12800 + 2 * 3840) * 4)

__global__ __launch_bounds__(256) void k2_mlp(
    const float* __restrict__ x,
    const float* __restrict__ o1w, const float* __restrict__ o1b,
    const float* __restrict__ o2w, const float* __restrict__ o2b,
    float* __restrict__ out)
{
    extern __shared__ float sm[];
    unsigned* Au = (unsigned*)sm;            // 128*100 w
    unsigned* Bu = Au + 12800;               // 128*100 w
    unsigned* Wu = Bu + 12800;               // 2 * 192*20 w
    float*    F  = sm;                       // fp32 final stage, stride 200

    const int tid = threadIdx.x;
    const int m0  = blockIdx.x * TM;
    const int bi  = m0 / NN;
    const int warp = tid >> 5, lane = tid & 31;
    const int gid = lane >> 2, tig = lane & 3;
    const int m0w = (warp >> 1) * 32, n0w = (warp & 1) * 96;

    const float* Mb = g_M + (size_t)bi * CC * CC;
    const float* cvb = g_cvec + bi * CC;

    for (int idx = tid; idx < TM * 24; idx += 256) {
        int p = idx / 24, seg = idx % 24;
        const float* xp = &x[(size_t)(m0 + p) * CC + seg * 8];
        float4 v0 = *(const float4*)xp;
        float4 v1 = *(const float4*)(xp + 4);
        unsigned* dst = Au + p * AW + seg * 4;
        dst[0] = pk2h(v0.x, v0.y); dst[1] = pk2h(v0.z, v0.w);
        dst[2] = pk2h(v1.x, v1.y); dst[3] = pk2h(v1.z, v1.w);
    }
    __syncthreads();

    float4 wrv[3];
    float acc[2][12][4];

    auto zeroacc = [&]() {
        #pragma unroll
        for (int i = 0; i < 2; i++)
            #pragma unroll
            for (int j = 0; j < 12; j++)
                #pragma unroll
                for (int e = 0; e < 4; e++) acc[i][j][e] = 0.f;
    };
    auto ldgW = [&](const float* W, int k0) {
        #pragma unroll
        for (int t = 0; t < 3; t++) {
            int idx = tid + t * 256;
            int d = idx >> 2, seg = idx & 3;
            wrv[t] = *(const float4*)&W[(size_t)d * CC + k0 + seg * 4];
        }
    };
    auto stsW = [&](int buf) {
        #pragma unroll
        for (int t = 0; t < 3; t++) {
            int idx = tid + t * 256;
            int d = idx >> 2, seg = idx & 3;
            unsigned* dst = Wu + buf * 3840 + d * 20 + seg * 2;
            dst[0] = pk2h(wrv[t].x, wrv[t].y);
            dst[1] = pk2h(wrv[t].z, wrv[t].w);
        }
    };
    auto mmachunk = [&](const unsigned* Asrc, int c, int buf) {
        const unsigned* Wb = Wu + buf * 3840;
        int kw = c * 8;
        unsigned a[2][4];
        #pragma unroll
        for (int i = 0; i < 2; i++) {
            const unsigned* ap = Asrc + (m0w + 16 * i + gid) * AW + kw + tig;
            a[i][0] = ap[0];
            a[i][1] = ap[8 * AW];
            a[i][2] = ap[4];
            a[i][3] = ap[8 * AW + 4];
        }
        #pragma unroll
        for (int j = 0; j < 12; j++) {
            const unsigned* bp = Wb + (n0w + 8 * j + gid) * 20 + tig;
            unsigned b0 = bp[0], b1 = bp[4];
            mma16(acc[0][j], a[0][0], a[0][1], a[0][2], a[0][3], b0, b1);
            mma16(acc[1][j], a[1][0], a[1][1], a[1][2], a[1][3], b0, b1);
        }
    };
    auto gemm = [&](const unsigned* Asrc, const float* W) {
        zeroacc();
        ldgW(W, 0);
        #pragma unroll 1
        for (int c = 0; c < 12; c++) {
            stsW(c & 1);
            if (c < 11) ldgW(W, (c + 1) * 16);
            __syncthreads();
            mmachunk(Asrc, c, c & 1);
        }
    };

    // GEMM0: ret = x @ M^T + cvec + fp16(x) -> Bu
    gemm(Au, Mb);
    #pragma unroll
    for (int j = 0; j < 12; j++) {
        int c0 = n0w + 8 * j + 2 * tig;
        float cv0 = __ldg(&cvb[c0]);
        float cv1 = __ldg(&cvb[c0 + 1]);
        #pragma unroll
        for (int i = 0; i < 2; i++) {
            int r = m0w + 16 * i + gid;
            float2 x0 = up2f(Au[r * AW + (c0 >> 1)]);
            float2 x1 = up2f(Au[(r + 8) * AW + (c0 >> 1)]);
            Bu[r * AW + (c0 >> 1)]       = pk2h(acc[i][j][0] + cv0 + x0.x, acc[i][j][1] + cv1 + x0.y);
            Bu[(r + 8) * AW + (c0 >> 1)] = pk2h(acc[i][j][2] + cv0 + x1.x, acc[i][j][3] + cv1 + x1.y);
        }
    }

    // GEMM1: h = gelu(ret @ o1w^T + o1b) -> Au
    gemm(Bu, o1w);
    #pragma unroll
    for (int j = 0; j < 12; j++) {
        int c0 = n0w + 8 * j + 2 * tig;
        float b0 = __ldg(&o1b[c0]);
        float b1 = __ldg(&o1b[c0 + 1]);
        #pragma unroll
        for (int i = 0; i < 2; i++) {
            int r = m0w + 16 * i + gid;
            float t0 = acc[i][j][0] + b0;
            float t1 = acc[i][j][1] + b1;
            float t2 = acc[i][j][2] + b0;
            float t3 = acc[i][j][3] + b1;
            float g0 = 0.5f * t0 * (1.f + erff(t0 * 0.70710678118654752f));
            float g1 = 0.5f * t1 * (1.f + erff(t1 * 0.70710678118654752f));
            float g2 = 0.5f * t2 * (1.f + erff(t2 * 0.70710678118654752f));
            float g3 = 0.5f * t3 * (1.f + erff(t3 * 0.70710678118654752f));
            Au[r * AW + (c0 >> 1)]       = pk2h(g0, g1);
            Au[(r + 8) * AW + (c0 >> 1)] = pk2h(g2, g3);
        }
    }

    // GEMM2: out = h @ o2w^T + o2b + exact x
    gemm(Au, o2w);
    __syncthreads();

    #pragma unroll
    for (int j = 0; j < 12; j++) {
        int c0 = n0w + 8 * j + 2 * tig;
        #pragma unroll
        for (int i = 0; i < 2; i++) {
            int r = m0w + 16 * i + gid;
            *(float2*)&F[r * 200 + c0]       = make_float2(acc[i][j][0], acc[i][j][1]);
            *(float2*)&F[(r + 8) * 200 + c0] = make_float2(acc[i][j][2], acc[i][j][3]);
        }
    }
    __syncthreads();

    for (int idx = tid; idx < TM * 48; idx += 256) {
        int p = idx / 48, c4 = (idx % 48) * 4;
        float4 av = *(float4*)&F[p * 200 + c4];
        float4 bv = *(const float4*)&o2b[c4];
        float4 xv = *(const float4*)&x[(size_t)(m0 + p) * CC + c4];
        av.x += bv.x + xv.x;
        av.y += bv.y + xv.y;
        av.z += bv.z + xv.z;
        av.w += bv.w + xv.w;
        *(float4*)&out[(size_t)(m0 + p) * CC + c4] = av;
    }
}

// ---------------------------------------------------------------------------

extern "C" void kernel_launch(void* const* d_in, const int* in_sizes, int n_in,
                              void* d_out, int out_size)
{
    const float* x     = (const float*)d_in[0];
    const float* qkv_w = (const float*)d_in[1];
    const float* qkv_b = (const float*)d_in[2];
    const float* o1w   = (const float*)d_in[3];
    const float* o1b   = (const float*)d_in[4];
    const float* o2w   = (const float*)d_in[5];
    const float* o2b   = (const float*)d_in[6];
    const float* klw   = (const float*)d_in[7];
    const float* klb   = (const float*)d_in[8];
    const float* vlw   = (const float*)d_in[9];
    const float* vlb   = (const float*)d_in[10];
    float* out = (float*)d_out;

    cudaFuncSetAttribute(k1_kv, cudaFuncAttributeMaxDynamicSharedMemorySize, K1_SMEM);
    cudaFuncSetAttribute(k2_mlp, cudaFuncAttributeMaxDynamicSharedMemorySize, K2_SMEM);

    zero_kv_kernel<<<(BB * HEADS * HEADC * HEADC + 255) / 256, 256>>>();

    dim3 g1(HEADS / 2, MTOT / TM);
    k1_kv<<<g1, 256, K1_SMEM>>>(x, qkv_w, qkv_b, klw, klb, vlw, vlb);

    k_mid<<<BB * HEADS, 256>>>(qkv_w, qkv_b);

    k2_mlp<<<MTOT / TM, 256, K2_SMEM>>>(x, o1w, o1b, o2w, o2b, out);
}